// round 6
// baseline (speedup 1.0000x reference)
#include <cuda_runtime.h>
#include <cuda_fp16.h>

#define HIDDEN    64
#define N_USERS   100000
#define N_MOVIES  50000
#define MOVIE_FEAT 128
#define N_EDGES   2000000
#define N_LABEL   500000

// padded so the single-block scans can read int4 past n without guards
#define NM_PAD (N_MOVIES + 8192)
#define NU_PAD (N_USERS  + 8192)

// ---------------- device scratch (allocation-free rule: __device__ globals) ----------------
// g_deg_* are zero at module load and re-zeroed by scan_kernel after each consumption,
// so every execution of kernel_launch sees them zeroed.
__device__ __align__(16) int g_deg_m[NM_PAD];
__device__ __align__(16) int g_deg_u[NU_PAD];
__device__ __align__(16) int g_off_m[NM_PAD];
__device__ __align__(16) int g_off_u[NU_PAD];
__device__ __align__(16) int g_cur_m[NM_PAD];
__device__ __align__(16) int g_cur_u[NU_PAD];
__device__ int g_csr_m[N_EDGES];   // neighbors (user idx) of each movie, CSR by movie
__device__ int g_csr_u[N_EDGES];   // neighbors (movie idx) of each user, CSR by user
// fp16 node feature buffers; fp32 buffers hold means, then (layer 2, in-place) final outputs
__device__ __align__(16) __half g_x16u[N_USERS  * HIDDEN];
__device__ __align__(16) __half g_x16m[N_MOVIES * HIDDEN];
__device__ __align__(16) __half g_h16u[N_USERS  * HIDDEN];
__device__ __align__(16) __half g_h16m[N_MOVIES * HIDDEN];
__device__ __align__(16) float g_mu[N_USERS  * HIDDEN];
__device__ __align__(16) float g_mm[N_MOVIES * HIDDEN];

// ---------------- packed f32x2 helpers ----------------
__device__ __forceinline__ unsigned long long pack2(float lo, float hi)
{
    unsigned long long r;
    asm("mov.b64 %0, {%1, %2};" : "=l"(r) : "f"(lo), "f"(hi));
    return r;
}
__device__ __forceinline__ void unpack2(unsigned long long v, float& lo, float& hi)
{
    asm("mov.b64 {%0, %1}, %2;" : "=f"(lo), "=f"(hi) : "l"(v));
}
__device__ __forceinline__ unsigned long long ffma2(unsigned long long a,
                                                    unsigned long long b,
                                                    unsigned long long c)
{
    unsigned long long d;
    asm("fma.rn.f32x2 %0, %1, %2, %3;" : "=l"(d) : "l"(a), "l"(b), "l"(c));
    return d;
}
__device__ __forceinline__ unsigned long long fadd2(unsigned long long a,
                                                    unsigned long long b)
{
    unsigned long long d;
    asm("add.rn.f32x2 %0, %1, %2;" : "=l"(d) : "l"(a), "l"(b));
    return d;
}

// ---------------- CSR build ----------------
__global__ void hist_kernel(const int4* __restrict__ src4, const int4* __restrict__ dst4)
{
    int i = blockIdx.x * blockDim.x + threadIdx.x;
    if (i >= N_EDGES / 4) return;
    int4 s = __ldg(src4 + i), d = __ldg(dst4 + i);
    atomicAdd(&g_deg_u[s.x], 1); atomicAdd(&g_deg_u[s.y], 1);
    atomicAdd(&g_deg_u[s.z], 1); atomicAdd(&g_deg_u[s.w], 1);
    atomicAdd(&g_deg_m[d.x], 1); atomicAdd(&g_deg_m[d.y], 1);
    atomicAdd(&g_deg_m[d.z], 1); atomicAdd(&g_deg_m[d.w], 1);
}

// block 0 scans movie degrees, block 1 scans user degrees; initializes cursors and
// re-zeroes the degree arrays (each thread zeroes its own chunk after reading it).
__global__ __launch_bounds__(1024) void scan_kernel()
{
    int n; int* deg; int* off; int* cur;
    if (blockIdx.x == 0) { n = N_MOVIES; deg = g_deg_m; off = g_off_m; cur = g_cur_m; }
    else                 { n = N_USERS;  deg = g_deg_u; off = g_off_u; cur = g_cur_u; }
    int chunk = ((((n + 1023) >> 10) + 3) & ~3);   // multiple of 4 for int4
    int t = threadIdx.x;
    int start = t * chunk;

    int s = 0;
    for (int i = 0; i < chunk; i += 4) {
        int4 v = *(const int4*)(deg + start + i);
        s += v.x + v.y + v.z + v.w;
    }
    __shared__ int sh[1024];
    sh[t] = s; __syncthreads();
    for (int d = 1; d < 1024; d <<= 1) {
        int v = (t >= d) ? sh[t - d] : 0;
        __syncthreads();
        sh[t] += v;
        __syncthreads();
    }
    int run = t ? sh[t - 1] : 0;
    int4 z = make_int4(0, 0, 0, 0);
    for (int i = 0; i < chunk; i += 4) {
        int4 v = *(const int4*)(deg + start + i);
        int4 o;
        o.x = run; run += v.x;
        o.y = run; run += v.y;
        o.z = run; run += v.z;
        o.w = run; run += v.w;
        *(int4*)(off + start + i) = o;
        *(int4*)(cur + start + i) = o;
        *(int4*)(deg + start + i) = z;   // ready for the next execution's hist
    }
}

__global__ void scatter_kernel(const int4* __restrict__ src4, const int4* __restrict__ dst4)
{
    int i = blockIdx.x * blockDim.x + threadIdx.x;
    if (i >= N_EDGES / 4) return;
    int4 s = __ldg(src4 + i), d = __ldg(dst4 + i);
    g_csr_m[atomicAdd(&g_cur_m[d.x], 1)] = s.x;
    g_csr_u[atomicAdd(&g_cur_u[s.x], 1)] = d.x;
    g_csr_m[atomicAdd(&g_cur_m[d.y], 1)] = s.y;
    g_csr_u[atomicAdd(&g_cur_u[s.y], 1)] = d.y;
    g_csr_m[atomicAdd(&g_cur_m[d.z], 1)] = s.z;
    g_csr_u[atomicAdd(&g_cur_u[s.z], 1)] = d.z;
    g_csr_m[atomicAdd(&g_cur_m[d.w], 1)] = s.w;
    g_csr_u[atomicAdd(&g_cur_u[s.w], 1)] = d.w;
}

// ---------------- feature init ----------------
__global__ void gather_user_kernel(const float* __restrict__ emb,
                                   const int* __restrict__ nid,
                                   __half* __restrict__ xu16)
{
    int i = blockIdx.x * blockDim.x + threadIdx.x;   // over N_USERS*16 float4s
    if (i >= N_USERS * 16) return;
    int r = i >> 4, c = i & 15;
    float4 v = __ldg((const float4*)emb + nid[r] * 16 + c);
    __half2 h0 = __floats2half2_rn(v.x, v.y);
    __half2 h1 = __floats2half2_rn(v.z, v.w);
    uint2 o;
    o.x = *(unsigned int*)&h0;
    o.y = *(unsigned int*)&h1;
    ((uint2*)xu16)[i] = o;
}

// x_movie = movie_x @ lin_W^T + lin_b + movie_emb[movie_nid]
__global__ __launch_bounds__(256) void movie_init_kernel(
    const float* __restrict__ movie_x, const float* __restrict__ lin_W,
    const float* __restrict__ lin_b,  const float* __restrict__ movie_emb,
    const int* __restrict__ movie_nid, __half* __restrict__ xm16, int n)
{
    __shared__ float4 srow[4][8][32];
    int j = threadIdx.x & 63, g = threadIdx.x >> 6;
    unsigned long long w01[32], w23[32];
#pragma unroll
    for (int k = 0; k < 32; k++) {
        float4 t = __ldg((const float4*)lin_W + j * 32 + k);
        w01[k] = pack2(t.x, t.y);
        w23[k] = pack2(t.z, t.w);
    }
    float bj = __ldg(lin_b + j);
    for (int r0 = blockIdx.x * 32; r0 < n; r0 += gridDim.x * 32) {
        int rbase = r0 + g * 8;
#pragma unroll
        for (int p = 0; p < 4; p++) {
            int item = p * 64 + j;
            int row = item >> 5, col = item & 31;
            int r = rbase + row;
            if (r < n)
                srow[g][row][col] = __ldg((const float4*)movie_x + (size_t)r * 32 + col);
        }
        __syncthreads();
#pragma unroll
        for (int rr = 0; rr < 8; rr++) {
            int r = rbase + rr;
            if (r < n) {
                unsigned long long p0 = 0, p1 = 0;
#pragma unroll
                for (int k = 0; k < 32; k++) {
                    ulonglong2 v = *(const ulonglong2*)&srow[g][rr][k];
                    p0 = ffma2(v.x, w01[k], p0);
                    p1 = ffma2(v.y, w23[k], p1);
                }
                float a0, a1, a2, a3;
                unpack2(p0, a0, a1); unpack2(p1, a2, a3);
                int nid = __ldg(movie_nid + r);
                float res = (a0 + a1) + (a2 + a3) + bj +
                            __ldg(movie_emb + (size_t)nid * 64 + j);
                xm16[(size_t)r * 64 + j] = __float2half(res);
            }
        }
        __syncthreads();
    }
}

// ---------------- segment mean, full warp per node, predicated 16-row chunks --------------
// lane reads one half2 (4B) -> whole warp reads one 128B line per row. Invalid rows in the
// last chunk load 0 (half2(0,0)) and contribute nothing, so there is no remainder loop and
// 16 independent lines stay in flight through the tail.
__global__ void aggregate2_kernel(const __half* __restrict__ src_for_m,  // user feats fp16
                                  const __half* __restrict__ src_for_u,  // movie feats fp16
                                  float* __restrict__ out_m, float* __restrict__ out_u)
{
    int w = (blockIdx.x * blockDim.x + threadIdx.x) >> 5;
    int lane = threadIdx.x & 31;
    const unsigned* xsrc; const int* csr; const int* off; float2* mean; int node;
    if (w < N_MOVIES) {
        node = w; xsrc = (const unsigned*)src_for_m; csr = g_csr_m; off = g_off_m;
        mean = (float2*)out_m;
    } else {
        node = w - N_MOVIES;
        if (node >= N_USERS) return;
        xsrc = (const unsigned*)src_for_u; csr = g_csr_u; off = g_off_u;
        mean = (float2*)out_u;
    }
    int s0 = __ldg(off + node);
    int deg = __ldg(off + node + 1) - s0;
    const int* nb = csr + s0;

    unsigned long long acc0 = 0, acc1 = 0, acc2 = 0, acc3 = 0;
    int nch = (deg + 15) >> 4;
    int idx[16];
#pragma unroll
    for (int k = 0; k < 16; k++)
        idx[k] = (k < deg) ? __ldg(nb + k) : -1;
    for (int c = 0; c < nch; c++) {
        unsigned v[16];
#pragma unroll
        for (int k = 0; k < 16; k++)
            v[k] = (idx[k] >= 0) ? __ldg(xsrc + (size_t)idx[k] * 32 + lane) : 0u;
#pragma unroll
        for (int k = 0; k < 16; k++) {
            int i2 = (c + 1) * 16 + k;
            idx[k] = (i2 < deg) ? __ldg(nb + i2) : -1;
        }
#pragma unroll
        for (int k = 0; k < 16; k += 4) {
            float2 f0 = __half22float2(*(const __half2*)&v[k]);
            float2 f1 = __half22float2(*(const __half2*)&v[k + 1]);
            float2 f2 = __half22float2(*(const __half2*)&v[k + 2]);
            float2 f3 = __half22float2(*(const __half2*)&v[k + 3]);
            acc0 = fadd2(acc0, pack2(f0.x, f0.y));
            acc1 = fadd2(acc1, pack2(f1.x, f1.y));
            acc2 = fadd2(acc2, pack2(f2.x, f2.y));
            acc3 = fadd2(acc3, pack2(f3.x, f3.y));
        }
    }
    float a0, a1, b0, b1, c0, c1, d0, d1;
    unpack2(acc0, a0, a1); unpack2(acc1, b0, b1);
    unpack2(acc2, c0, c1); unpack2(acc3, d0, d1);
    float inv = deg > 0 ? 1.0f / (float)deg : 0.0f;   // deg==0 -> mean 0, matches reference
    float2 o;
    o.x = ((a0 + b0) + (c0 + d0)) * inv;
    o.y = ((a1 + b1) + (c1 + d1)) * inv;
    mean[(size_t)node * 32 + lane] = o;
}

// ---------------- SAGE transform via mma.sync m16n8k16 (fp16 in, fp32 accum) --------------
#define A_STRIDE 136   // halfs per A/B smem row (128 + 8 pad -> conflict-free frag loads)

template<bool L1>
__global__ __launch_bounds__(256) void mma_transform_kernel(
    const float* __restrict__ mean_m, const __half* __restrict__ xd_m,
    const float* __restrict__ Wl_m, const float* __restrict__ bl_m,
    const float* __restrict__ Wr_m, __half* __restrict__ o16_m, float* __restrict__ o32_m,
    const float* __restrict__ mean_u, const __half* __restrict__ xd_u,
    const float* __restrict__ Wl_u, const float* __restrict__ bl_u,
    const float* __restrict__ Wr_u, __half* __restrict__ o16_u, float* __restrict__ o32_u,
    int nb_m)
{
    extern __shared__ char smem[];
    __half* As = (__half*)smem;                       // [128][A_STRIDE]
    __half* Bs = As + 128 * A_STRIDE;                 // [64][A_STRIDE]
    float* bias_s = (float*)(Bs + 64 * A_STRIDE);     // [64]

    const float *mean, *Wl, *bl, *Wr; const __half* xd; __half* o16; float* o32;
    int n, base;
    if ((int)blockIdx.x < nb_m) {
        mean = mean_m; xd = xd_m; Wl = Wl_m; bl = bl_m; Wr = Wr_m;
        o16 = o16_m; o32 = o32_m; n = N_MOVIES; base = blockIdx.x * 128;
    } else {
        mean = mean_u; xd = xd_u; Wl = Wl_u; bl = bl_u; Wr = Wr_u;
        o16 = o16_u; o32 = o32_u; n = N_USERS; base = (blockIdx.x - nb_m) * 128;
    }
    int tid = threadIdx.x;

    // stage B: 64 j-rows x 64 half2 pairs
#pragma unroll
    for (int t = 0; t < 16; t++) {
        int idx = t * 256 + tid;
        int j = idx >> 6, p = idx & 63;
        int k = 2 * p;
        float2 w;
        if (k < 64) w = __ldg((const float2*)(Wl + j * 64 + k));
        else        w = __ldg((const float2*)(Wr + j * 64 + (k - 64)));
        *(__half2*)(Bs + j * A_STRIDE + k) = __floats2half2_rn(w.x, w.y);
    }
    if (tid < 64) bias_s[tid] = __ldg(bl + tid);

    // stage A mean part: 128 rows x 32 half2 pairs (cols 0..63)
#pragma unroll
    for (int t = 0; t < 16; t++) {
        int idx = t * 256 + tid;
        int r = idx >> 5, p = idx & 31;
        __half2 h = __floats2half2_rn(0.f, 0.f);
        if (base + r < n) {
            float2 v = __ldg((const float2*)(mean + (size_t)(base + r) * 64 + 2 * p));
            h = __floats2half2_rn(v.x, v.y);
        }
        *(__half2*)(As + r * A_STRIDE + 2 * p) = h;
    }
    // stage A x part: 128 rows x 8 uint4 (cols 64..127, fp16 direct)
#pragma unroll
    for (int t = 0; t < 4; t++) {
        int idx = t * 256 + tid;
        int r = idx >> 3, q = idx & 7;
        uint4 u = make_uint4(0, 0, 0, 0);
        if (base + r < n)
            u = __ldg((const uint4*)(xd + (size_t)(base + r) * 64) + q);
        *(uint4*)(As + r * A_STRIDE + 64 + q * 8) = u;
    }
    __syncthreads();

    int warp = tid >> 5, lane = tid & 31;
    int grp = lane >> 2, tig = lane & 3;
    int r0 = warp * 16;
    float acc[8][4];
#pragma unroll
    for (int nt = 0; nt < 8; nt++)
#pragma unroll
        for (int c = 0; c < 4; c++) acc[nt][c] = 0.f;

#pragma unroll
    for (int kt = 0; kt < 8; kt++) {
        int ar = r0 + grp, ac = kt * 16 + tig * 2;
        unsigned a0 = *(const unsigned*)(As + ar * A_STRIDE + ac);
        unsigned a1 = *(const unsigned*)(As + (ar + 8) * A_STRIDE + ac);
        unsigned a2 = *(const unsigned*)(As + ar * A_STRIDE + ac + 8);
        unsigned a3 = *(const unsigned*)(As + (ar + 8) * A_STRIDE + ac + 8);
#pragma unroll
        for (int nt = 0; nt < 8; nt++) {
            int bn = nt * 8 + grp, bk = kt * 16 + tig * 2;
            unsigned b0 = *(const unsigned*)(Bs + bn * A_STRIDE + bk);
            unsigned b1 = *(const unsigned*)(Bs + bn * A_STRIDE + bk + 8);
            asm volatile(
                "mma.sync.aligned.m16n8k16.row.col.f32.f16.f16.f32 "
                "{%0,%1,%2,%3}, {%4,%5,%6,%7}, {%8,%9}, {%0,%1,%2,%3};"
                : "+f"(acc[nt][0]), "+f"(acc[nt][1]), "+f"(acc[nt][2]), "+f"(acc[nt][3])
                : "r"(a0), "r"(a1), "r"(a2), "r"(a3), "r"(b0), "r"(b1));
        }
    }

    // epilogue
#pragma unroll
    for (int nt = 0; nt < 8; nt++) {
        int col = nt * 8 + tig * 2;
        float bj0 = bias_s[col], bj1 = bias_s[col + 1];
        int gr0 = base + r0 + grp;
        int gr1 = gr0 + 8;
        float v00 = acc[nt][0] + bj0, v01 = acc[nt][1] + bj1;
        float v10 = acc[nt][2] + bj0, v11 = acc[nt][3] + bj1;
        if (L1) {
            v00 = fmaxf(v00, 0.f); v01 = fmaxf(v01, 0.f);
            v10 = fmaxf(v10, 0.f); v11 = fmaxf(v11, 0.f);
            if (gr0 < n) *(__half2*)(o16 + (size_t)gr0 * 64 + col) = __floats2half2_rn(v00, v01);
            if (gr1 < n) *(__half2*)(o16 + (size_t)gr1 * 64 + col) = __floats2half2_rn(v10, v11);
        } else {
            if (gr0 < n) *(float2*)(o32 + (size_t)gr0 * 64 + col) = make_float2(v00, v01);
            if (gr1 < n) *(float2*)(o32 + (size_t)gr1 * 64 + col) = make_float2(v10, v11);
        }
    }
}

// ---------------- dot-product decoder (half-warp per edge, fp32 inputs) ----------------
__global__ void decode_kernel(const float* __restrict__ ou, const float* __restrict__ om,
                              const int* __restrict__ ls, const int* __restrict__ ld,
                              float* __restrict__ out, int n)
{
    int e = (blockIdx.x * blockDim.x + threadIdx.x) >> 4;
    int lane = threadIdx.x & 15;
    if (e >= n) return;
    int u = __ldg(ls + e), m = __ldg(ld + e);
    float4 a = __ldg((const float4*)ou + (size_t)u * 16 + lane);
    float4 b = __ldg((const float4*)om + (size_t)m * 16 + lane);
    float p = a.x * b.x + a.y * b.y + a.z * b.z + a.w * b.w;
    p += __shfl_xor_sync(0xffffffffu, p, 1);
    p += __shfl_xor_sync(0xffffffffu, p, 2);
    p += __shfl_xor_sync(0xffffffffu, p, 4);
    p += __shfl_xor_sync(0xffffffffu, p, 8);
    if (lane == 0) out[e] = p;
}

// ---------------- launch ----------------
extern "C" void kernel_launch(void* const* d_in, const int* in_sizes, int n_in,
                              void* d_out, int out_size)
{
    const float* movie_x   = (const float*)d_in[0];
    const int*   user_nid  = (const int*)d_in[1];
    const int*   movie_nid = (const int*)d_in[2];
    const int*   e_src     = (const int*)d_in[3];
    const int*   e_dst     = (const int*)d_in[4];
    const int*   l_src     = (const int*)d_in[5];
    const int*   l_dst     = (const int*)d_in[6];
    const float* user_emb  = (const float*)d_in[7];
    const float* movie_emb = (const float*)d_in[8];
    const float* lin_W     = (const float*)d_in[9];
    const float* lin_b     = (const float*)d_in[10];
    const float* W_l_um1 = (const float*)d_in[11];
    const float* b_l_um1 = (const float*)d_in[12];
    const float* W_r_um1 = (const float*)d_in[13];
    const float* W_l_mu1 = (const float*)d_in[14];
    const float* b_l_mu1 = (const float*)d_in[15];
    const float* W_r_mu1 = (const float*)d_in[16];
    const float* W_l_um2 = (const float*)d_in[17];
    const float* b_l_um2 = (const float*)d_in[18];
    const float* W_r_um2 = (const float*)d_in[19];
    const float* W_l_mu2 = (const float*)d_in[20];
    const float* b_l_mu2 = (const float*)d_in[21];
    const float* W_r_mu2 = (const float*)d_in[22];
    float* out = (float*)d_out;

    float *mu, *mm;
    __half *x16u, *x16m, *h16u, *h16m;
    cudaGetSymbolAddress((void**)&mu, g_mu);
    cudaGetSymbolAddress((void**)&mm, g_mm);
    cudaGetSymbolAddress((void**)&x16u, g_x16u);
    cudaGetSymbolAddress((void**)&x16m, g_x16m);
    cudaGetSymbolAddress((void**)&h16u, g_h16u);
    cudaGetSymbolAddress((void**)&h16m, g_h16m);

    const int MMA_SMEM = (128 * A_STRIDE + 64 * A_STRIDE) * 2 + 64 * 4;  // 52480B
    cudaFuncSetAttribute(mma_transform_kernel<true>,
                         cudaFuncAttributeMaxDynamicSharedMemorySize, MMA_SMEM);
    cudaFuncSetAttribute(mma_transform_kernel<false>,
                         cudaFuncAttributeMaxDynamicSharedMemorySize, MMA_SMEM);

    // CSR build; g_deg_* arrive zeroed (module load / previous scan_kernel)
    hist_kernel<<<(N_EDGES / 4 + 255) / 256, 256>>>((const int4*)e_src, (const int4*)e_dst);
    scan_kernel<<<2, 1024>>>();   // writes off+cur, re-zeroes deg

    // feature init (independent of scatter; movie_init lands at profiled launch slot 3)
    gather_user_kernel<<<(N_USERS * 16 + 255) / 256, 256>>>(user_emb, user_nid, x16u);
    movie_init_kernel<<<592, 256>>>(movie_x, lin_W, lin_b, movie_emb, movie_nid,
                                    x16m, N_MOVIES);

    scatter_kernel<<<(N_EDGES / 4 + 255) / 256, 256>>>((const int4*)e_src, (const int4*)e_dst);

    const int AGG_BLOCKS = ((N_MOVIES + N_USERS) * 32 + 255) / 256;
    const int NB_M = (N_MOVIES + 127) / 128;   // 391
    const int NB_U = (N_USERS + 127) / 128;    // 782

    // layer 1 (+relu), fp16 outputs
    aggregate2_kernel<<<AGG_BLOCKS, 256>>>(x16u, x16m, mm, mu);
    mma_transform_kernel<true><<<NB_M + NB_U, 256, MMA_SMEM>>>(
        mm, x16m, W_l_um1, b_l_um1, W_r_um1, h16m, nullptr,
        mu, x16u, W_l_mu1, b_l_mu1, W_r_mu1, h16u, nullptr, NB_M);

    // layer 2 (no activation), fp32 outputs in-place over the mean buffers
    aggregate2_kernel<<<AGG_BLOCKS, 256>>>(h16u, h16m, mm, mu);
    mma_transform_kernel<false><<<NB_M + NB_U, 256, MMA_SMEM>>>(
        mm, h16m, W_l_um2, b_l_um2, W_r_um2, nullptr, mm,
        mu, h16u, W_l_mu2, b_l_mu2, W_r_mu2, nullptr, mu, NB_M);

    // decoder (fp32 finals: users in mu, movies in mm)
    decode_kernel<<<(N_LABEL * 16 + 255) / 256, 256>>>(mu, mm, l_src, l_dst, out, N_LABEL);
}

// round 7
// speedup vs baseline: 1.3110x; 1.3110x over previous
#include <cuda_runtime.h>
#include <cuda_fp16.h>

#define HIDDEN    64
#define N_USERS   100000
#define N_MOVIES  50000
#define MOVIE_FEAT 128
#define N_EDGES   2000000
#define N_LABEL   500000

// padded so the single-block scans can read int4 past n without guards
#define NM_PAD (N_MOVIES + 8192)
#define NU_PAD (N_USERS  + 8192)

// ---------------- device scratch (allocation-free rule: __device__ globals) ----------------
// g_deg_* are zero at module load and re-zeroed by scan_kernel after each consumption,
// so every execution of kernel_launch sees them zeroed.
__device__ __align__(16) int g_deg_m[NM_PAD];
__device__ __align__(16) int g_deg_u[NU_PAD];
__device__ __align__(16) int g_off_m[NM_PAD];
__device__ __align__(16) int g_off_u[NU_PAD];
__device__ __align__(16) int g_cur_m[NM_PAD];
__device__ __align__(16) int g_cur_u[NU_PAD];
__device__ int g_csr_m[N_EDGES];   // neighbors (user idx) of each movie, CSR by movie
__device__ int g_csr_u[N_EDGES];   // neighbors (movie idx) of each user, CSR by user
// fp16 node feature buffers; fp32 buffers hold means, then (layer 2, in-place) final outputs
__device__ __align__(16) __half g_x16u[N_USERS  * HIDDEN];
__device__ __align__(16) __half g_x16m[N_MOVIES * HIDDEN];
__device__ __align__(16) __half g_h16u[N_USERS  * HIDDEN];
__device__ __align__(16) __half g_h16m[N_MOVIES * HIDDEN];
__device__ __align__(16) float g_mu[N_USERS  * HIDDEN];
__device__ __align__(16) float g_mm[N_MOVIES * HIDDEN];

// ---------------- packed f32x2 helpers ----------------
__device__ __forceinline__ unsigned long long pack2(float lo, float hi)
{
    unsigned long long r;
    asm("mov.b64 %0, {%1, %2};" : "=l"(r) : "f"(lo), "f"(hi));
    return r;
}
__device__ __forceinline__ void unpack2(unsigned long long v, float& lo, float& hi)
{
    asm("mov.b64 {%0, %1}, %2;" : "=f"(lo), "=f"(hi) : "l"(v));
}
__device__ __forceinline__ unsigned long long fadd2(unsigned long long a,
                                                    unsigned long long b)
{
    unsigned long long d;
    asm("add.rn.f32x2 %0, %1, %2;" : "=l"(d) : "l"(a), "l"(b));
    return d;
}

// ---------------- CSR build ----------------
__global__ void hist_kernel(const int4* __restrict__ src4, const int4* __restrict__ dst4)
{
    int i = blockIdx.x * blockDim.x + threadIdx.x;
    if (i >= N_EDGES / 4) return;
    int4 s = __ldg(src4 + i), d = __ldg(dst4 + i);
    atomicAdd(&g_deg_u[s.x], 1); atomicAdd(&g_deg_u[s.y], 1);
    atomicAdd(&g_deg_u[s.z], 1); atomicAdd(&g_deg_u[s.w], 1);
    atomicAdd(&g_deg_m[d.x], 1); atomicAdd(&g_deg_m[d.y], 1);
    atomicAdd(&g_deg_m[d.z], 1); atomicAdd(&g_deg_m[d.w], 1);
}

// block 0 scans movie degrees, block 1 scans user degrees; initializes cursors and
// re-zeroes the degree arrays (each thread zeroes its own chunk after reading it).
__global__ __launch_bounds__(1024) void scan_kernel()
{
    int n; int* deg; int* off; int* cur;
    if (blockIdx.x == 0) { n = N_MOVIES; deg = g_deg_m; off = g_off_m; cur = g_cur_m; }
    else                 { n = N_USERS;  deg = g_deg_u; off = g_off_u; cur = g_cur_u; }
    int chunk = ((((n + 1023) >> 10) + 3) & ~3);   // multiple of 4 for int4
    int t = threadIdx.x;
    int start = t * chunk;

    int s = 0;
    for (int i = 0; i < chunk; i += 4) {
        int4 v = *(const int4*)(deg + start + i);
        s += v.x + v.y + v.z + v.w;
    }
    __shared__ int sh[1024];
    sh[t] = s; __syncthreads();
    for (int d = 1; d < 1024; d <<= 1) {
        int v = (t >= d) ? sh[t - d] : 0;
        __syncthreads();
        sh[t] += v;
        __syncthreads();
    }
    int run = t ? sh[t - 1] : 0;
    int4 z = make_int4(0, 0, 0, 0);
    for (int i = 0; i < chunk; i += 4) {
        int4 v = *(const int4*)(deg + start + i);
        int4 o;
        o.x = run; run += v.x;
        o.y = run; run += v.y;
        o.z = run; run += v.z;
        o.w = run; run += v.w;
        *(int4*)(off + start + i) = o;
        *(int4*)(cur + start + i) = o;
        *(int4*)(deg + start + i) = z;   // ready for the next execution's hist
    }
}

__global__ void scatter_kernel(const int4* __restrict__ src4, const int4* __restrict__ dst4)
{
    int i = blockIdx.x * blockDim.x + threadIdx.x;
    if (i >= N_EDGES / 4) return;
    int4 s = __ldg(src4 + i), d = __ldg(dst4 + i);
    g_csr_m[atomicAdd(&g_cur_m[d.x], 1)] = s.x;
    g_csr_u[atomicAdd(&g_cur_u[s.x], 1)] = d.x;
    g_csr_m[atomicAdd(&g_cur_m[d.y], 1)] = s.y;
    g_csr_u[atomicAdd(&g_cur_u[s.y], 1)] = d.y;
    g_csr_m[atomicAdd(&g_cur_m[d.z], 1)] = s.z;
    g_csr_u[atomicAdd(&g_cur_u[s.z], 1)] = d.z;
    g_csr_m[atomicAdd(&g_cur_m[d.w], 1)] = s.w;
    g_csr_u[atomicAdd(&g_cur_u[s.w], 1)] = d.w;
}

// ---------------- feature init ----------------
__global__ void gather_user_kernel(const float* __restrict__ emb,
                                   const int* __restrict__ nid,
                                   __half* __restrict__ xu16)
{
    int i = blockIdx.x * blockDim.x + threadIdx.x;   // over N_USERS*16 float4s
    if (i >= N_USERS * 16) return;
    int r = i >> 4, c = i & 15;
    float4 v = __ldg((const float4*)emb + nid[r] * 16 + c);
    __half2 h0 = __floats2half2_rn(v.x, v.y);
    __half2 h1 = __floats2half2_rn(v.z, v.w);
    uint2 o;
    o.x = *(unsigned int*)&h0;
    o.y = *(unsigned int*)&h1;
    ((uint2*)xu16)[i] = o;
}

#define A_STRIDE 136   // halfs per MMA smem row (128 + 8 pad -> conflict-free frag loads)

// x_movie = movie_x @ lin_W^T + lin_b + movie_emb[movie_nid], via tensor cores with
// hi/lo fp16 split of BOTH operands (3 MMAs) -> effectively fp32-accurate result.
// One 128-row tile per block, 8 warps x 16 rows.
__global__ __launch_bounds__(256) void movie_init_mma_kernel(
    const float* __restrict__ movie_x, const float* __restrict__ lin_W,
    const float* __restrict__ lin_b,  const float* __restrict__ movie_emb,
    const int* __restrict__ movie_nid, __half* __restrict__ xm16, int n)
{
    extern __shared__ char smem[];
    __half* Ah = (__half*)smem;                    // [128][A_STRIDE]
    __half* Al = Ah + 128 * A_STRIDE;              // [128][A_STRIDE]
    __half* Bh = Al + 128 * A_STRIDE;              // [64][A_STRIDE]
    __half* Bl = Bh + 64 * A_STRIDE;               // [64][A_STRIDE]
    float* bias_s = (float*)(Bl + 64 * A_STRIDE);  // [64]
    int* snid = (int*)(bias_s + 64);               // [128]

    int tid = threadIdx.x;
    int base = blockIdx.x * 128;

    // stage A: 128 rows x 64 float2 = 8192 items
#pragma unroll
    for (int t = 0; t < 32; t++) {
        int idx = t * 256 + tid;
        int r = idx >> 6, p = idx & 63;    // p-th float2 pair of the 128-float row
        float2 v = make_float2(0.f, 0.f);
        if (base + r < n)
            v = __ldg((const float2*)movie_x + (size_t)(base + r) * 64 + p);
        __half2 hi = __floats2half2_rn(v.x, v.y);
        float2 hf = __half22float2(hi);
        __half2 lo = __floats2half2_rn(v.x - hf.x, v.y - hf.y);
        *(__half2*)(Ah + r * A_STRIDE + 2 * p) = hi;
        *(__half2*)(Al + r * A_STRIDE + 2 * p) = lo;
    }
    // stage B: 64 j-rows x 64 float2 = 4096 items (lin_W is [64][128] row-major)
#pragma unroll
    for (int t = 0; t < 16; t++) {
        int idx = t * 256 + tid;
        int j = idx >> 6, p = idx & 63;
        float2 w = __ldg((const float2*)lin_W + j * 64 + p);
        __half2 hi = __floats2half2_rn(w.x, w.y);
        float2 hf = __half22float2(hi);
        __half2 lo = __floats2half2_rn(w.x - hf.x, w.y - hf.y);
        *(__half2*)(Bh + j * A_STRIDE + 2 * p) = hi;
        *(__half2*)(Bl + j * A_STRIDE + 2 * p) = lo;
    }
    if (tid < 64) bias_s[tid] = __ldg(lin_b + tid);
    if (tid < 128) {
        int r = base + tid;
        snid[tid] = __ldg(movie_nid + (r < n ? r : 0));
    }
    __syncthreads();

    int warp = tid >> 5, lane = tid & 31;
    int grp = lane >> 2, tig = lane & 3;
    int r0 = warp * 16;
    float acc[8][4];
#pragma unroll
    for (int nt = 0; nt < 8; nt++)
#pragma unroll
        for (int c = 0; c < 4; c++) acc[nt][c] = 0.f;

#pragma unroll
    for (int kt = 0; kt < 8; kt++) {
        int ar = r0 + grp, ac = kt * 16 + tig * 2;
        unsigned ah0 = *(const unsigned*)(Ah + ar * A_STRIDE + ac);
        unsigned ah1 = *(const unsigned*)(Ah + (ar + 8) * A_STRIDE + ac);
        unsigned ah2 = *(const unsigned*)(Ah + ar * A_STRIDE + ac + 8);
        unsigned ah3 = *(const unsigned*)(Ah + (ar + 8) * A_STRIDE + ac + 8);
        unsigned al0 = *(const unsigned*)(Al + ar * A_STRIDE + ac);
        unsigned al1 = *(const unsigned*)(Al + (ar + 8) * A_STRIDE + ac);
        unsigned al2 = *(const unsigned*)(Al + ar * A_STRIDE + ac + 8);
        unsigned al3 = *(const unsigned*)(Al + (ar + 8) * A_STRIDE + ac + 8);
#pragma unroll
        for (int nt = 0; nt < 8; nt++) {
            int bn = nt * 8 + grp, bk = kt * 16 + tig * 2;
            unsigned bh0 = *(const unsigned*)(Bh + bn * A_STRIDE + bk);
            unsigned bh1 = *(const unsigned*)(Bh + bn * A_STRIDE + bk + 8);
            unsigned bl0 = *(const unsigned*)(Bl + bn * A_STRIDE + bk);
            unsigned bl1 = *(const unsigned*)(Bl + bn * A_STRIDE + bk + 8);
            asm volatile(
                "mma.sync.aligned.m16n8k16.row.col.f32.f16.f16.f32 "
                "{%0,%1,%2,%3}, {%4,%5,%6,%7}, {%8,%9}, {%0,%1,%2,%3};"
                : "+f"(acc[nt][0]), "+f"(acc[nt][1]), "+f"(acc[nt][2]), "+f"(acc[nt][3])
                : "r"(ah0), "r"(ah1), "r"(ah2), "r"(ah3), "r"(bh0), "r"(bh1));
            asm volatile(
                "mma.sync.aligned.m16n8k16.row.col.f32.f16.f16.f32 "
                "{%0,%1,%2,%3}, {%4,%5,%6,%7}, {%8,%9}, {%0,%1,%2,%3};"
                : "+f"(acc[nt][0]), "+f"(acc[nt][1]), "+f"(acc[nt][2]), "+f"(acc[nt][3])
                : "r"(al0), "r"(al1), "r"(al2), "r"(al3), "r"(bh0), "r"(bh1));
            asm volatile(
                "mma.sync.aligned.m16n8k16.row.col.f32.f16.f16.f32 "
                "{%0,%1,%2,%3}, {%4,%5,%6,%7}, {%8,%9}, {%0,%1,%2,%3};"
                : "+f"(acc[nt][0]), "+f"(acc[nt][1]), "+f"(acc[nt][2]), "+f"(acc[nt][3])
                : "r"(ah0), "r"(ah1), "r"(ah2), "r"(ah3), "r"(bl0), "r"(bl1));
        }
    }

    // epilogue: + bias + movie_emb[nid] gather, fp16 out
#pragma unroll
    for (int nt = 0; nt < 8; nt++) {
        int col = nt * 8 + tig * 2;
        float bj0 = bias_s[col], bj1 = bias_s[col + 1];
        int lr0 = r0 + grp, lr1 = lr0 + 8;
        int gr0 = base + lr0, gr1 = base + lr1;
        if (gr0 < n) {
            float2 e = __ldg((const float2*)movie_emb + (size_t)snid[lr0] * 32 + col / 2);
            *(__half2*)(xm16 + (size_t)gr0 * 64 + col) =
                __floats2half2_rn(acc[nt][0] + bj0 + e.x, acc[nt][1] + bj1 + e.y);
        }
        if (gr1 < n) {
            float2 e = __ldg((const float2*)movie_emb + (size_t)snid[lr1] * 32 + col / 2);
            *(__half2*)(xm16 + (size_t)gr1 * 64 + col) =
                __floats2half2_rn(acc[nt][2] + bj0 + e.x, acc[nt][3] + bj1 + e.y);
        }
    }
}

// ---------------- segment mean, both directions fused, software-pipelined ----------------
// half-warp per node; 8 independent feature loads in flight; next index chunk prefetched
// while the current chunk's feature loads are outstanding. (R5 version — fastest measured.)
__global__ void aggregate2_kernel(const __half* __restrict__ src_for_m,  // user feats fp16
                                  const __half* __restrict__ src_for_u,  // movie feats fp16
                                  float* __restrict__ out_m, float* __restrict__ out_u)
{
    int h = (blockIdx.x * blockDim.x + threadIdx.x) >> 4;
    int lane = threadIdx.x & 15;
    const uint2* xsrc; const int* csr; const int* off; float4* mean; int node;
    if (h < N_MOVIES) {
        node = h; xsrc = (const uint2*)src_for_m; csr = g_csr_m; off = g_off_m;
        mean = (float4*)out_m;
    } else {
        node = h - N_MOVIES;
        if (node >= N_USERS) return;
        xsrc = (const uint2*)src_for_u; csr = g_csr_u; off = g_off_u;
        mean = (float4*)out_u;
    }
    int s0 = __ldg(off + node);
    int deg = __ldg(off + node + 1) - s0;
    const int* nb = csr + s0;

    unsigned long long a01 = 0, a23 = 0, b01 = 0, b23 = 0;
    int nch = deg >> 3;
    int idx[8];
    if (nch > 0) {
#pragma unroll
        for (int k = 0; k < 8; k++) idx[k] = __ldg(nb + k);
        for (int c = 0; c < nch; c++) {
            uint2 v[8];
#pragma unroll
            for (int k = 0; k < 8; k++)
                v[k] = __ldg(xsrc + (size_t)idx[k] * 16 + lane);
            if (c + 1 < nch) {
                const int* p = nb + (c + 1) * 8;
#pragma unroll
                for (int k = 0; k < 8; k++) idx[k] = __ldg(p + k);
            }
#pragma unroll
            for (int k = 0; k < 8; k++) {
                float2 lo = __half22float2(*(const __half2*)&v[k].x);
                float2 hi = __half22float2(*(const __half2*)&v[k].y);
                if (k & 1) {
                    b01 = fadd2(b01, pack2(lo.x, lo.y));
                    b23 = fadd2(b23, pack2(hi.x, hi.y));
                } else {
                    a01 = fadd2(a01, pack2(lo.x, lo.y));
                    a23 = fadd2(a23, pack2(hi.x, hi.y));
                }
            }
        }
    }
    for (int i = nch * 8; i < deg; i++) {
        int n0 = __ldg(nb + i);
        uint2 v = __ldg(xsrc + (size_t)n0 * 16 + lane);
        float2 lo = __half22float2(*(const __half2*)&v.x);
        float2 hi = __half22float2(*(const __half2*)&v.y);
        a01 = fadd2(a01, pack2(lo.x, lo.y));
        a23 = fadd2(a23, pack2(hi.x, hi.y));
    }
    float a0, a1, a2, a3, b0, b1, b2, b3;
    unpack2(a01, a0, a1); unpack2(a23, a2, a3);
    unpack2(b01, b0, b1); unpack2(b23, b2, b3);
    float inv = deg > 0 ? 1.0f / (float)deg : 0.0f;   // deg==0 -> mean 0, matches reference
    float4 o;
    o.x = (a0 + b0) * inv; o.y = (a1 + b1) * inv;
    o.z = (a2 + b2) * inv; o.w = (a3 + b3) * inv;
    mean[(size_t)node * 16 + lane] = o;
}

// ---------------- SAGE transform via mma.sync m16n8k16 (fp16 in, fp32 accum) --------------
template<bool L1>
__global__ __launch_bounds__(256) void mma_transform_kernel(
    const float* __restrict__ mean_m, const __half* __restrict__ xd_m,
    const float* __restrict__ Wl_m, const float* __restrict__ bl_m,
    const float* __restrict__ Wr_m, __half* __restrict__ o16_m, float* __restrict__ o32_m,
    const float* __restrict__ mean_u, const __half* __restrict__ xd_u,
    const float* __restrict__ Wl_u, const float* __restrict__ bl_u,
    const float* __restrict__ Wr_u, __half* __restrict__ o16_u, float* __restrict__ o32_u,
    int nb_m)
{
    extern __shared__ char smem[];
    __half* As = (__half*)smem;                       // [128][A_STRIDE]
    __half* Bs = As + 128 * A_STRIDE;                 // [64][A_STRIDE]
    float* bias_s = (float*)(Bs + 64 * A_STRIDE);     // [64]

    const float *mean, *Wl, *bl, *Wr; const __half* xd; __half* o16; float* o32;
    int n, base;
    if ((int)blockIdx.x < nb_m) {
        mean = mean_m; xd = xd_m; Wl = Wl_m; bl = bl_m; Wr = Wr_m;
        o16 = o16_m; o32 = o32_m; n = N_MOVIES; base = blockIdx.x * 128;
    } else {
        mean = mean_u; xd = xd_u; Wl = Wl_u; bl = bl_u; Wr = Wr_u;
        o16 = o16_u; o32 = o32_u; n = N_USERS; base = (blockIdx.x - nb_m) * 128;
    }
    int tid = threadIdx.x;

    // stage B: 64 j-rows x 64 half2 pairs
#pragma unroll
    for (int t = 0; t < 16; t++) {
        int idx = t * 256 + tid;
        int j = idx >> 6, p = idx & 63;
        int k = 2 * p;
        float2 w;
        if (k < 64) w = __ldg((const float2*)(Wl + j * 64 + k));
        else        w = __ldg((const float2*)(Wr + j * 64 + (k - 64)));
        *(__half2*)(Bs + j * A_STRIDE + k) = __floats2half2_rn(w.x, w.y);
    }
    if (tid < 64) bias_s[tid] = __ldg(bl + tid);

    // stage A mean part: 128 rows x 32 half2 pairs (cols 0..63)
#pragma unroll
    for (int t = 0; t < 16; t++) {
        int idx = t * 256 + tid;
        int r = idx >> 5, p = idx & 31;
        __half2 h = __floats2half2_rn(0.f, 0.f);
        if (base + r < n) {
            float2 v = __ldg((const float2*)(mean + (size_t)(base + r) * 64 + 2 * p));
            h = __floats2half2_rn(v.x, v.y);
        }
        *(__half2*)(As + r * A_STRIDE + 2 * p) = h;
    }
    // stage A x part: 128 rows x 8 uint4 (cols 64..127, fp16 direct)
#pragma unroll
    for (int t = 0; t < 4; t++) {
        int idx = t * 256 + tid;
        int r = idx >> 3, q = idx & 7;
        uint4 u = make_uint4(0, 0, 0, 0);
        if (base + r < n)
            u = __ldg((const uint4*)(xd + (size_t)(base + r) * 64) + q);
        *(uint4*)(As + r * A_STRIDE + 64 + q * 8) = u;
    }
    __syncthreads();

    int warp = tid >> 5, lane = tid & 31;
    int grp = lane >> 2, tig = lane & 3;
    int r0 = warp * 16;
    float acc[8][4];
#pragma unroll
    for (int nt = 0; nt < 8; nt++)
#pragma unroll
        for (int c = 0; c < 4; c++) acc[nt][c] = 0.f;

#pragma unroll
    for (int kt = 0; kt < 8; kt++) {
        int ar = r0 + grp, ac = kt * 16 + tig * 2;
        unsigned a0 = *(const unsigned*)(As + ar * A_STRIDE + ac);
        unsigned a1 = *(const unsigned*)(As + (ar + 8) * A_STRIDE + ac);
        unsigned a2 = *(const unsigned*)(As + ar * A_STRIDE + ac + 8);
        unsigned a3 = *(const unsigned*)(As + (ar + 8) * A_STRIDE + ac + 8);
#pragma unroll
        for (int nt = 0; nt < 8; nt++) {
            int bn = nt * 8 + grp, bk = kt * 16 + tig * 2;
            unsigned b0 = *(const unsigned*)(Bs + bn * A_STRIDE + bk);
            unsigned b1 = *(const unsigned*)(Bs + bn * A_STRIDE + bk + 8);
            asm volatile(
                "mma.sync.aligned.m16n8k16.row.col.f32.f16.f16.f32 "
                "{%0,%1,%2,%3}, {%4,%5,%6,%7}, {%8,%9}, {%0,%1,%2,%3};"
                : "+f"(acc[nt][0]), "+f"(acc[nt][1]), "+f"(acc[nt][2]), "+f"(acc[nt][3])
                : "r"(a0), "r"(a1), "r"(a2), "r"(a3), "r"(b0), "r"(b1));
        }
    }

    // epilogue
#pragma unroll
    for (int nt = 0; nt < 8; nt++) {
        int col = nt * 8 + tig * 2;
        float bj0 = bias_s[col], bj1 = bias_s[col + 1];
        int gr0 = base + r0 + grp;
        int gr1 = gr0 + 8;
        float v00 = acc[nt][0] + bj0, v01 = acc[nt][1] + bj1;
        float v10 = acc[nt][2] + bj0, v11 = acc[nt][3] + bj1;
        if (L1) {
            v00 = fmaxf(v00, 0.f); v01 = fmaxf(v01, 0.f);
            v10 = fmaxf(v10, 0.f); v11 = fmaxf(v11, 0.f);
            if (gr0 < n) *(__half2*)(o16 + (size_t)gr0 * 64 + col) = __floats2half2_rn(v00, v01);
            if (gr1 < n) *(__half2*)(o16 + (size_t)gr1 * 64 + col) = __floats2half2_rn(v10, v11);
        } else {
            if (gr0 < n) *(float2*)(o32 + (size_t)gr0 * 64 + col) = make_float2(v00, v01);
            if (gr1 < n) *(float2*)(o32 + (size_t)gr1 * 64 + col) = make_float2(v10, v11);
        }
    }
}

// ---------------- dot-product decoder (half-warp per edge, fp32 inputs) ----------------
__global__ void decode_kernel(const float* __restrict__ ou, const float* __restrict__ om,
                              const int* __restrict__ ls, const int* __restrict__ ld,
                              float* __restrict__ out, int n)
{
    int e = (blockIdx.x * blockDim.x + threadIdx.x) >> 4;
    int lane = threadIdx.x & 15;
    if (e >= n) return;
    int u = __ldg(ls + e), m = __ldg(ld + e);
    float4 a = __ldg((const float4*)ou + (size_t)u * 16 + lane);
    float4 b = __ldg((const float4*)om + (size_t)m * 16 + lane);
    float p = a.x * b.x + a.y * b.y + a.z * b.z + a.w * b.w;
    p += __shfl_xor_sync(0xffffffffu, p, 1);
    p += __shfl_xor_sync(0xffffffffu, p, 2);
    p += __shfl_xor_sync(0xffffffffu, p, 4);
    p += __shfl_xor_sync(0xffffffffu, p, 8);
    if (lane == 0) out[e] = p;
}

// ---------------- launch ----------------
extern "C" void kernel_launch(void* const* d_in, const int* in_sizes, int n_in,
                              void* d_out, int out_size)
{
    const float* movie_x   = (const float*)d_in[0];
    const int*   user_nid  = (const int*)d_in[1];
    const int*   movie_nid = (const int*)d_in[2];
    const int*   e_src     = (const int*)d_in[3];
    const int*   e_dst     = (const int*)d_in[4];
    const int*   l_src     = (const int*)d_in[5];
    const int*   l_dst     = (const int*)d_in[6];
    const float* user_emb  = (const float*)d_in[7];
    const float* movie_emb = (const float*)d_in[8];
    const float* lin_W     = (const float*)d_in[9];
    const float* lin_b     = (const float*)d_in[10];
    const float* W_l_um1 = (const float*)d_in[11];
    const float* b_l_um1 = (const float*)d_in[12];
    const float* W_r_um1 = (const float*)d_in[13];
    const float* W_l_mu1 = (const float*)d_in[14];
    const float* b_l_mu1 = (const float*)d_in[15];
    const float* W_r_mu1 = (const float*)d_in[16];
    const float* W_l_um2 = (const float*)d_in[17];
    const float* b_l_um2 = (const float*)d_in[18];
    const float* W_r_um2 = (const float*)d_in[19];
    const float* W_l_mu2 = (const float*)d_in[20];
    const float* b_l_mu2 = (const float*)d_in[21];
    const float* W_r_mu2 = (const float*)d_in[22];
    float* out = (float*)d_out;

    float *mu, *mm;
    __half *x16u, *x16m, *h16u, *h16m;
    cudaGetSymbolAddress((void**)&mu, g_mu);
    cudaGetSymbolAddress((void**)&mm, g_mm);
    cudaGetSymbolAddress((void**)&x16u, g_x16u);
    cudaGetSymbolAddress((void**)&x16m, g_x16m);
    cudaGetSymbolAddress((void**)&h16u, g_h16u);
    cudaGetSymbolAddress((void**)&h16m, g_h16m);

    const int MMA_SMEM = (128 * A_STRIDE + 64 * A_STRIDE) * 2 + 64 * 4;  // 52480B
    const int MI_SMEM = (128 * A_STRIDE + 64 * A_STRIDE) * 2 * 2 + 64 * 4 + 128 * 4;
    cudaFuncSetAttribute(mma_transform_kernel<true>,
                         cudaFuncAttributeMaxDynamicSharedMemorySize, MMA_SMEM);
    cudaFuncSetAttribute(mma_transform_kernel<false>,
                         cudaFuncAttributeMaxDynamicSharedMemorySize, MMA_SMEM);
    cudaFuncSetAttribute(movie_init_mma_kernel,
                         cudaFuncAttributeMaxDynamicSharedMemorySize, MI_SMEM);

    const int NB_M = (N_MOVIES + 127) / 128;   // 391
    const int NB_U = (N_USERS + 127) / 128;    // 782

    // CSR build; g_deg_* arrive zeroed (module load / previous scan_kernel)
    hist_kernel<<<(N_EDGES / 4 + 255) / 256, 256>>>((const int4*)e_src, (const int4*)e_dst);
    scan_kernel<<<2, 1024>>>();   // writes off+cur, re-zeroes deg

    // feature init (movie_init lands at profiled launch slot 3 to verify the MMA rewrite)
    gather_user_kernel<<<(N_USERS * 16 + 255) / 256, 256>>>(user_emb, user_nid, x16u);
    movie_init_mma_kernel<<<NB_M, 256, MI_SMEM>>>(movie_x, lin_W, lin_b, movie_emb,
                                                  movie_nid, x16m, N_MOVIES);

    scatter_kernel<<<(N_EDGES / 4 + 255) / 256, 256>>>((const int4*)e_src, (const int4*)e_dst);

    const int AGG_BLOCKS = ((N_MOVIES + N_USERS) * 16 + 255) / 256;

    // layer 1 (+relu), fp16 outputs
    aggregate2_kernel<<<AGG_BLOCKS, 256>>>(x16u, x16m, mm, mu);
    mma_transform_kernel<true><<<NB_M + NB_U, 256, MMA_SMEM>>>(
        mm, x16m, W_l_um1, b_l_um1, W_r_um1, h16m, nullptr,
        mu, x16u, W_l_mu1, b_l_mu1, W_r_mu1, h16u, nullptr, NB_M);

    // layer 2 (no activation), fp32 outputs in-place over the mean buffers
    aggregate2_kernel<<<AGG_BLOCKS, 256>>>(h16u, h16m, mm, mu);
    mma_transform_kernel<false><<<NB_M + NB_U, 256, MMA_SMEM>>>(
        mm, h16m, W_l_um2, b_l_um2, W_r_um2, nullptr, mm,
        mu, h16u, W_l_mu2, b_l_mu2, W_r_mu2, nullptr, mu, NB_M);

    // decoder (fp32 finals: users in mu, movies in mm)
    decode_kernel<<<(N_LABEL * 16 + 255) / 256, 256>>>(mu, mm, l_src, l_dst, out, N_LABEL);
}

// round 8
// speedup vs baseline: 1.3549x; 1.0334x over previous
#include <cuda_runtime.h>
#include <cuda_fp16.h>

#define HIDDEN    64
#define N_USERS   100000
#define N_MOVIES  50000
#define MOVIE_FEAT 128
#define N_EDGES   2000000
#define N_LABEL   500000

// padded so the single-block scans can read int4 past n without guards
#define NM_PAD (N_MOVIES + 8192)
#define NU_PAD (N_USERS  + 8192)

// ---------------- device scratch (allocation-free rule: __device__ globals) ----------------
// g_deg_* are zero at module load and re-zeroed by scan_kernel after each consumption,
// so every execution of kernel_launch sees them zeroed.
__device__ __align__(16) int g_deg_m[NM_PAD];
__device__ __align__(16) int g_deg_u[NU_PAD];
__device__ __align__(16) int g_off_m[NM_PAD];
__device__ __align__(16) int g_off_u[NU_PAD];
__device__ __align__(16) int g_cur_m[NM_PAD];
__device__ __align__(16) int g_cur_u[NU_PAD];
__device__ int g_csr_m[N_EDGES];   // neighbors (user idx) of each movie, CSR by movie
__device__ int g_csr_u[N_EDGES];   // neighbors (movie idx) of each user, CSR by user
// fp16 node feature buffers; fp32 buffers hold means, then (layer 2, in-place) final outputs
__device__ __align__(16) __half g_x16u[N_USERS  * HIDDEN];
__device__ __align__(16) __half g_x16m[N_MOVIES * HIDDEN];
__device__ __align__(16) __half g_h16u[N_USERS  * HIDDEN];
__device__ __align__(16) __half g_h16m[N_MOVIES * HIDDEN];
__device__ __align__(16) float g_mu[N_USERS  * HIDDEN];
__device__ __align__(16) float g_mm[N_MOVIES * HIDDEN];

// ---------------- packed f32x2 helpers ----------------
__device__ __forceinline__ unsigned long long pack2(float lo, float hi)
{
    unsigned long long r;
    asm("mov.b64 %0, {%1, %2};" : "=l"(r) : "f"(lo), "f"(hi));
    return r;
}
__device__ __forceinline__ void unpack2(unsigned long long v, float& lo, float& hi)
{
    asm("mov.b64 {%0, %1}, %2;" : "=f"(lo), "=f"(hi) : "l"(v));
}
__device__ __forceinline__ unsigned long long fadd2(unsigned long long a,
                                                    unsigned long long b)
{
    unsigned long long d;
    asm("add.rn.f32x2 %0, %1, %2;" : "=l"(d) : "l"(a), "l"(b));
    return d;
}

#define A_STRIDE 136   // halfs per MMA smem row (128 + 8 pad -> conflict-free frag loads)
#define NB_M_CONST ((N_MOVIES + 127) / 128)          // 391 movie-init blocks
#define GU_BLOCKS  ((N_USERS * 16 + 255) / 256)      // 6250 gather blocks
#define HIST_BLOCKS ((N_EDGES / 4 + 255) / 256)      // 1954 hist blocks

// ---------------- fused init: movie_init(MMA) | gather_user | hist ----------------
// Three mutually independent jobs in one launch, split by blockIdx.x, so the hist's
// L2-atomic traffic overlaps the tensor-core init and the embedding-gather copies.
__global__ __launch_bounds__(256) void fused_init_kernel(
    const float* __restrict__ movie_x, const float* __restrict__ lin_W,
    const float* __restrict__ lin_b,  const float* __restrict__ movie_emb,
    const int* __restrict__ movie_nid, __half* __restrict__ xm16,
    const float* __restrict__ user_emb, const int* __restrict__ user_nid,
    __half* __restrict__ xu16,
    const int4* __restrict__ src4, const int4* __restrict__ dst4)
{
    int tid = threadIdx.x;

    if (blockIdx.x >= NB_M_CONST) {
        int b = blockIdx.x - NB_M_CONST;
        if (b < GU_BLOCKS) {
            // ---- gather_user: x_user = user_emb[user_nid] (fp16) ----
            int i = b * 256 + tid;
            if (i >= N_USERS * 16) return;
            int r = i >> 4, c = i & 15;
            float4 v = __ldg((const float4*)user_emb + __ldg(user_nid + r) * 16 + c);
            __half2 h0 = __floats2half2_rn(v.x, v.y);
            __half2 h1 = __floats2half2_rn(v.z, v.w);
            uint2 o;
            o.x = *(unsigned int*)&h0;
            o.y = *(unsigned int*)&h1;
            ((uint2*)xu16)[i] = o;
        } else {
            // ---- hist: degree histogram of both directions ----
            int i = (b - GU_BLOCKS) * 256 + tid;
            if (i >= N_EDGES / 4) return;
            int4 s = __ldg(src4 + i), d = __ldg(dst4 + i);
            atomicAdd(&g_deg_u[s.x], 1); atomicAdd(&g_deg_u[s.y], 1);
            atomicAdd(&g_deg_u[s.z], 1); atomicAdd(&g_deg_u[s.w], 1);
            atomicAdd(&g_deg_m[d.x], 1); atomicAdd(&g_deg_m[d.y], 1);
            atomicAdd(&g_deg_m[d.z], 1); atomicAdd(&g_deg_m[d.w], 1);
        }
        return;
    }

    // ---- movie_init via tensor cores, hi/lo fp16 split (3 MMAs, fp32-accurate) ----
    extern __shared__ char smem[];
    __half* Ah = (__half*)smem;                    // [128][A_STRIDE]
    __half* Al = Ah + 128 * A_STRIDE;              // [128][A_STRIDE]
    __half* Bh = Al + 128 * A_STRIDE;              // [64][A_STRIDE]
    __half* Bl = Bh + 64 * A_STRIDE;               // [64][A_STRIDE]
    float* bias_s = (float*)(Bl + 64 * A_STRIDE);  // [64]
    int* snid = (int*)(bias_s + 64);               // [128]

    const int n = N_MOVIES;
    int base = blockIdx.x * 128;

    // stage A: 128 rows x 64 float2 = 8192 items
#pragma unroll
    for (int t = 0; t < 32; t++) {
        int idx = t * 256 + tid;
        int r = idx >> 6, p = idx & 63;
        float2 v = make_float2(0.f, 0.f);
        if (base + r < n)
            v = __ldg((const float2*)movie_x + (size_t)(base + r) * 64 + p);
        __half2 hi = __floats2half2_rn(v.x, v.y);
        float2 hf = __half22float2(hi);
        __half2 lo = __floats2half2_rn(v.x - hf.x, v.y - hf.y);
        *(__half2*)(Ah + r * A_STRIDE + 2 * p) = hi;
        *(__half2*)(Al + r * A_STRIDE + 2 * p) = lo;
    }
    // stage B: 64 j-rows x 64 float2 = 4096 items (lin_W is [64][128] row-major)
#pragma unroll
    for (int t = 0; t < 16; t++) {
        int idx = t * 256 + tid;
        int j = idx >> 6, p = idx & 63;
        float2 w = __ldg((const float2*)lin_W + j * 64 + p);
        __half2 hi = __floats2half2_rn(w.x, w.y);
        float2 hf = __half22float2(hi);
        __half2 lo = __floats2half2_rn(w.x - hf.x, w.y - hf.y);
        *(__half2*)(Bh + j * A_STRIDE + 2 * p) = hi;
        *(__half2*)(Bl + j * A_STRIDE + 2 * p) = lo;
    }
    if (tid < 64) bias_s[tid] = __ldg(lin_b + tid);
    if (tid < 128) {
        int r = base + tid;
        snid[tid] = __ldg(movie_nid + (r < n ? r : 0));
    }
    __syncthreads();

    int warp = tid >> 5, lane = tid & 31;
    int grp = lane >> 2, tig = lane & 3;
    int r0 = warp * 16;
    float acc[8][4];
#pragma unroll
    for (int nt = 0; nt < 8; nt++)
#pragma unroll
        for (int c = 0; c < 4; c++) acc[nt][c] = 0.f;

#pragma unroll
    for (int kt = 0; kt < 8; kt++) {
        int ar = r0 + grp, ac = kt * 16 + tig * 2;
        unsigned ah0 = *(const unsigned*)(Ah + ar * A_STRIDE + ac);
        unsigned ah1 = *(const unsigned*)(Ah + (ar + 8) * A_STRIDE + ac);
        unsigned ah2 = *(const unsigned*)(Ah + ar * A_STRIDE + ac + 8);
        unsigned ah3 = *(const unsigned*)(Ah + (ar + 8) * A_STRIDE + ac + 8);
        unsigned al0 = *(const unsigned*)(Al + ar * A_STRIDE + ac);
        unsigned al1 = *(const unsigned*)(Al + (ar + 8) * A_STRIDE + ac);
        unsigned al2 = *(const unsigned*)(Al + ar * A_STRIDE + ac + 8);
        unsigned al3 = *(const unsigned*)(Al + (ar + 8) * A_STRIDE + ac + 8);
#pragma unroll
        for (int nt = 0; nt < 8; nt++) {
            int bn = nt * 8 + grp, bk = kt * 16 + tig * 2;
            unsigned bh0 = *(const unsigned*)(Bh + bn * A_STRIDE + bk);
            unsigned bh1 = *(const unsigned*)(Bh + bn * A_STRIDE + bk + 8);
            unsigned bl0 = *(const unsigned*)(Bl + bn * A_STRIDE + bk);
            unsigned bl1 = *(const unsigned*)(Bl + bn * A_STRIDE + bk + 8);
            asm volatile(
                "mma.sync.aligned.m16n8k16.row.col.f32.f16.f16.f32 "
                "{%0,%1,%2,%3}, {%4,%5,%6,%7}, {%8,%9}, {%0,%1,%2,%3};"
                : "+f"(acc[nt][0]), "+f"(acc[nt][1]), "+f"(acc[nt][2]), "+f"(acc[nt][3])
                : "r"(ah0), "r"(ah1), "r"(ah2), "r"(ah3), "r"(bh0), "r"(bh1));
            asm volatile(
                "mma.sync.aligned.m16n8k16.row.col.f32.f16.f16.f32 "
                "{%0,%1,%2,%3}, {%4,%5,%6,%7}, {%8,%9}, {%0,%1,%2,%3};"
                : "+f"(acc[nt][0]), "+f"(acc[nt][1]), "+f"(acc[nt][2]), "+f"(acc[nt][3])
                : "r"(al0), "r"(al1), "r"(al2), "r"(al3), "r"(bh0), "r"(bh1));
            asm volatile(
                "mma.sync.aligned.m16n8k16.row.col.f32.f16.f16.f32 "
                "{%0,%1,%2,%3}, {%4,%5,%6,%7}, {%8,%9}, {%0,%1,%2,%3};"
                : "+f"(acc[nt][0]), "+f"(acc[nt][1]), "+f"(acc[nt][2]), "+f"(acc[nt][3])
                : "r"(ah0), "r"(ah1), "r"(ah2), "r"(ah3), "r"(bl0), "r"(bl1));
        }
    }

    // epilogue: + bias + movie_emb[nid] gather, fp16 out
#pragma unroll
    for (int nt = 0; nt < 8; nt++) {
        int col = nt * 8 + tig * 2;
        float bj0 = bias_s[col], bj1 = bias_s[col + 1];
        int lr0 = r0 + grp, lr1 = lr0 + 8;
        int gr0 = base + lr0, gr1 = base + lr1;
        if (gr0 < n) {
            float2 e = __ldg((const float2*)movie_emb + (size_t)snid[lr0] * 32 + col / 2);
            *(__half2*)(xm16 + (size_t)gr0 * 64 + col) =
                __floats2half2_rn(acc[nt][0] + bj0 + e.x, acc[nt][1] + bj1 + e.y);
        }
        if (gr1 < n) {
            float2 e = __ldg((const float2*)movie_emb + (size_t)snid[lr1] * 32 + col / 2);
            *(__half2*)(xm16 + (size_t)gr1 * 64 + col) =
                __floats2half2_rn(acc[nt][2] + bj0 + e.x, acc[nt][3] + bj1 + e.y);
        }
    }
}

// block 0 scans movie degrees, block 1 scans user degrees; initializes cursors and
// re-zeroes the degree arrays (each thread zeroes its own chunk after reading it).
__global__ __launch_bounds__(1024) void scan_kernel()
{
    int n; int* deg; int* off; int* cur;
    if (blockIdx.x == 0) { n = N_MOVIES; deg = g_deg_m; off = g_off_m; cur = g_cur_m; }
    else                 { n = N_USERS;  deg = g_deg_u; off = g_off_u; cur = g_cur_u; }
    int chunk = ((((n + 1023) >> 10) + 3) & ~3);   // multiple of 4 for int4
    int t = threadIdx.x;
    int start = t * chunk;

    int s = 0;
    for (int i = 0; i < chunk; i += 4) {
        int4 v = *(const int4*)(deg + start + i);
        s += v.x + v.y + v.z + v.w;
    }
    __shared__ int sh[1024];
    sh[t] = s; __syncthreads();
    for (int d = 1; d < 1024; d <<= 1) {
        int v = (t >= d) ? sh[t - d] : 0;
        __syncthreads();
        sh[t] += v;
        __syncthreads();
    }
    int run = t ? sh[t - 1] : 0;
    int4 z = make_int4(0, 0, 0, 0);
    for (int i = 0; i < chunk; i += 4) {
        int4 v = *(const int4*)(deg + start + i);
        int4 o;
        o.x = run; run += v.x;
        o.y = run; run += v.y;
        o.z = run; run += v.z;
        o.w = run; run += v.w;
        *(int4*)(off + start + i) = o;
        *(int4*)(cur + start + i) = o;
        *(int4*)(deg + start + i) = z;   // ready for the next execution's hist
    }
}

__global__ void scatter_kernel(const int4* __restrict__ src4, const int4* __restrict__ dst4)
{
    int i = blockIdx.x * blockDim.x + threadIdx.x;
    if (i >= N_EDGES / 4) return;
    int4 s = __ldg(src4 + i), d = __ldg(dst4 + i);
    g_csr_m[atomicAdd(&g_cur_m[d.x], 1)] = s.x;
    g_csr_u[atomicAdd(&g_cur_u[s.x], 1)] = d.x;
    g_csr_m[atomicAdd(&g_cur_m[d.y], 1)] = s.y;
    g_csr_u[atomicAdd(&g_cur_u[s.y], 1)] = d.y;
    g_csr_m[atomicAdd(&g_cur_m[d.z], 1)] = s.z;
    g_csr_u[atomicAdd(&g_cur_u[s.z], 1)] = d.z;
    g_csr_m[atomicAdd(&g_cur_m[d.w], 1)] = s.w;
    g_csr_u[atomicAdd(&g_cur_u[s.w], 1)] = d.w;
}

// ---------------- segment mean, both directions fused, software-pipelined ----------------
// half-warp per node; 8 independent feature loads in flight. All chunks (including the
// tail) are fully predicated: invalid rows load 0 under predicate, so there is no serial
// remainder loop and MLP stays 8 through the tail.
__global__ void aggregate2_kernel(const __half* __restrict__ src_for_m,  // user feats fp16
                                  const __half* __restrict__ src_for_u,  // movie feats fp16
                                  float* __restrict__ out_m, float* __restrict__ out_u)
{
    int h = (blockIdx.x * blockDim.x + threadIdx.x) >> 4;
    int lane = threadIdx.x & 15;
    const uint2* xsrc; const int* csr; const int* off; float4* mean; int node;
    if (h < N_MOVIES) {
        node = h; xsrc = (const uint2*)src_for_m; csr = g_csr_m; off = g_off_m;
        mean = (float4*)out_m;
    } else {
        node = h - N_MOVIES;
        if (node >= N_USERS) return;
        xsrc = (const uint2*)src_for_u; csr = g_csr_u; off = g_off_u;
        mean = (float4*)out_u;
    }
    int s0 = __ldg(off + node);
    int deg = __ldg(off + node + 1) - s0;
    const int* nb = csr + s0;

    unsigned long long a01 = 0, a23 = 0, b01 = 0, b23 = 0;
    int nch = (deg + 7) >> 3;
    int idx[8];
#pragma unroll
    for (int k = 0; k < 8; k++)
        idx[k] = (k < deg) ? __ldg(nb + k) : -1;
    for (int c = 0; c < nch; c++) {
        uint2 v[8];
#pragma unroll
        for (int k = 0; k < 8; k++)
            v[k] = (idx[k] >= 0) ? __ldg(xsrc + (size_t)idx[k] * 16 + lane)
                                 : make_uint2(0u, 0u);
#pragma unroll
        for (int k = 0; k < 8; k++) {
            int i2 = (c + 1) * 8 + k;
            idx[k] = (i2 < deg) ? __ldg(nb + i2) : -1;
        }
#pragma unroll
        for (int k = 0; k < 8; k++) {
            float2 lo = __half22float2(*(const __half2*)&v[k].x);
            float2 hi = __half22float2(*(const __half2*)&v[k].y);
            if (k & 1) {
                b01 = fadd2(b01, pack2(lo.x, lo.y));
                b23 = fadd2(b23, pack2(hi.x, hi.y));
            } else {
                a01 = fadd2(a01, pack2(lo.x, lo.y));
                a23 = fadd2(a23, pack2(hi.x, hi.y));
            }
        }
    }
    float a0, a1, a2, a3, b0, b1, b2, b3;
    unpack2(a01, a0, a1); unpack2(a23, a2, a3);
    unpack2(b01, b0, b1); unpack2(b23, b2, b3);
    float inv = deg > 0 ? 1.0f / (float)deg : 0.0f;   // deg==0 -> mean 0, matches reference
    float4 o;
    o.x = (a0 + b0) * inv; o.y = (a1 + b1) * inv;
    o.z = (a2 + b2) * inv; o.w = (a3 + b3) * inv;
    mean[(size_t)node * 16 + lane] = o;
}

// ---------------- SAGE transform via mma.sync m16n8k16 (fp16 in, fp32 accum) --------------
template<bool L1>
__global__ __launch_bounds__(256) void mma_transform_kernel(
    const float* __restrict__ mean_m, const __half* __restrict__ xd_m,
    const float* __restrict__ Wl_m, const float* __restrict__ bl_m,
    const float* __restrict__ Wr_m, __half* __restrict__ o16_m, float* __restrict__ o32_m,
    const float* __restrict__ mean_u, const __half* __restrict__ xd_u,
    const float* __restrict__ Wl_u, const float* __restrict__ bl_u,
    const float* __restrict__ Wr_u, __half* __restrict__ o16_u, float* __restrict__ o32_u,
    int nb_m)
{
    extern __shared__ char smem[];
    __half* As = (__half*)smem;                       // [128][A_STRIDE]
    __half* Bs = As + 128 * A_STRIDE;                 // [64][A_STRIDE]
    float* bias_s = (float*)(Bs + 64 * A_STRIDE);     // [64]

    const float *mean, *Wl, *bl, *Wr; const __half* xd; __half* o16; float* o32;
    int n, base;
    if ((int)blockIdx.x < nb_m) {
        mean = mean_m; xd = xd_m; Wl = Wl_m; bl = bl_m; Wr = Wr_m;
        o16 = o16_m; o32 = o32_m; n = N_MOVIES; base = blockIdx.x * 128;
    } else {
        mean = mean_u; xd = xd_u; Wl = Wl_u; bl = bl_u; Wr = Wr_u;
        o16 = o16_u; o32 = o32_u; n = N_USERS; base = (blockIdx.x - nb_m) * 128;
    }
    int tid = threadIdx.x;

    // stage B: 64 j-rows x 64 half2 pairs
#pragma unroll
    for (int t = 0; t < 16; t++) {
        int idx = t * 256 + tid;
        int j = idx >> 6, p = idx & 63;
        int k = 2 * p;
        float2 w;
        if (k < 64) w = __ldg((const float2*)(Wl + j * 64 + k));
        else        w = __ldg((const float2*)(Wr + j * 64 + (k - 64)));
        *(__half2*)(Bs + j * A_STRIDE + k) = __floats2half2_rn(w.x, w.y);
    }
    if (tid < 64) bias_s[tid] = __ldg(bl + tid);

    // stage A mean part: 128 rows x 32 half2 pairs (cols 0..63)
#pragma unroll
    for (int t = 0; t < 16; t++) {
        int idx = t * 256 + tid;
        int r = idx >> 5, p = idx & 31;
        __half2 h = __floats2half2_rn(0.f, 0.f);
        if (base + r < n) {
            float2 v = __ldg((const float2*)(mean + (size_t)(base + r) * 64 + 2 * p));
            h = __floats2half2_rn(v.x, v.y);
        }
        *(__half2*)(As + r * A_STRIDE + 2 * p) = h;
    }
    // stage A x part: 128 rows x 8 uint4 (cols 64..127, fp16 direct)
#pragma unroll
    for (int t = 0; t < 4; t++) {
        int idx = t * 256 + tid;
        int r = idx >> 3, q = idx & 7;
        uint4 u = make_uint4(0, 0, 0, 0);
        if (base + r < n)
            u = __ldg((const uint4*)(xd + (size_t)(base + r) * 64) + q);
        *(uint4*)(As + r * A_STRIDE + 64 + q * 8) = u;
    }
    __syncthreads();

    int warp = tid >> 5, lane = tid & 31;
    int grp = lane >> 2, tig = lane & 3;
    int r0 = warp * 16;
    float acc[8][4];
#pragma unroll
    for (int nt = 0; nt < 8; nt++)
#pragma unroll
        for (int c = 0; c < 4; c++) acc[nt][c] = 0.f;

#pragma unroll
    for (int kt = 0; kt < 8; kt++) {
        int ar = r0 + grp, ac = kt * 16 + tig * 2;
        unsigned a0 = *(const unsigned*)(As + ar * A_STRIDE + ac);
        unsigned a1 = *(const unsigned*)(As + (ar + 8) * A_STRIDE + ac);
        unsigned a2 = *(const unsigned*)(As + ar * A_STRIDE + ac + 8);
        unsigned a3 = *(const unsigned*)(As + (ar + 8) * A_STRIDE + ac + 8);
#pragma unroll
        for (int nt = 0; nt < 8; nt++) {
            int bn = nt * 8 + grp, bk = kt * 16 + tig * 2;
            unsigned b0 = *(const unsigned*)(Bs + bn * A_STRIDE + bk);
            unsigned b1 = *(const unsigned*)(Bs + bn * A_STRIDE + bk + 8);
            asm volatile(
                "mma.sync.aligned.m16n8k16.row.col.f32.f16.f16.f32 "
                "{%0,%1,%2,%3}, {%4,%5,%6,%7}, {%8,%9}, {%0,%1,%2,%3};"
                : "+f"(acc[nt][0]), "+f"(acc[nt][1]), "+f"(acc[nt][2]), "+f"(acc[nt][3])
                : "r"(a0), "r"(a1), "r"(a2), "r"(a3), "r"(b0), "r"(b1));
        }
    }

    // epilogue
#pragma unroll
    for (int nt = 0; nt < 8; nt++) {
        int col = nt * 8 + tig * 2;
        float bj0 = bias_s[col], bj1 = bias_s[col + 1];
        int gr0 = base + r0 + grp;
        int gr1 = gr0 + 8;
        float v00 = acc[nt][0] + bj0, v01 = acc[nt][1] + bj1;
        float v10 = acc[nt][2] + bj0, v11 = acc[nt][3] + bj1;
        if (L1) {
            v00 = fmaxf(v00, 0.f); v01 = fmaxf(v01, 0.f);
            v10 = fmaxf(v10, 0.f); v11 = fmaxf(v11, 0.f);
            if (gr0 < n) *(__half2*)(o16 + (size_t)gr0 * 64 + col) = __floats2half2_rn(v00, v01);
            if (gr1 < n) *(__half2*)(o16 + (size_t)gr1 * 64 + col) = __floats2half2_rn(v10, v11);
        } else {
            if (gr0 < n) *(float2*)(o32 + (size_t)gr0 * 64 + col) = make_float2(v00, v01);
            if (gr1 < n) *(float2*)(o32 + (size_t)gr1 * 64 + col) = make_float2(v10, v11);
        }
    }
}

// ---------------- dot-product decoder (half-warp per edge, fp32 inputs) ----------------
__global__ void decode_kernel(const float* __restrict__ ou, const float* __restrict__ om,
                              const int* __restrict__ ls, const int* __restrict__ ld,
                              float* __restrict__ out, int n)
{
    int e = (blockIdx.x * blockDim.x + threadIdx.x) >> 4;
    int lane = threadIdx.x & 15;
    if (e >= n) return;
    int u = __ldg(ls + e), m = __ldg(ld + e);
    float4 a = __ldg((const float4*)ou + (size_t)u * 16 + lane);
    float4 b = __ldg((const float4*)om + (size_t)m * 16 + lane);
    float p = a.x * b.x + a.y * b.y + a.z * b.z + a.w * b.w;
    p += __shfl_xor_sync(0xffffffffu, p, 1);
    p += __shfl_xor_sync(0xffffffffu, p, 2);
    p += __shfl_xor_sync(0xffffffffu, p, 4);
    p += __shfl_xor_sync(0xffffffffu, p, 8);
    if (lane == 0) out[e] = p;
}

// ---------------- launch ----------------
extern "C" void kernel_launch(void* const* d_in, const int* in_sizes, int n_in,
                              void* d_out, int out_size)
{
    const float* movie_x   = (const float*)d_in[0];
    const int*   user_nid  = (const int*)d_in[1];
    const int*   movie_nid = (const int*)d_in[2];
    const int*   e_src     = (const int*)d_in[3];
    const int*   e_dst     = (const int*)d_in[4];
    const int*   l_src     = (const int*)d_in[5];
    const int*   l_dst     = (const int*)d_in[6];
    const float* user_emb  = (const float*)d_in[7];
    const float* movie_emb = (const float*)d_in[8];
    const float* lin_W     = (const float*)d_in[9];
    const float* lin_b     = (const float*)d_in[10];
    const float* W_l_um1 = (const float*)d_in[11];
    const float* b_l_um1 = (const float*)d_in[12];
    const float* W_r_um1 = (const float*)d_in[13];
    const float* W_l_mu1 = (const float*)d_in[14];
    const float* b_l_mu1 = (const float*)d_in[15];
    const float* W_r_mu1 = (const float*)d_in[16];
    const float* W_l_um2 = (const float*)d_in[17];
    const float* b_l_um2 = (const float*)d_in[18];
    const float* W_r_um2 = (const float*)d_in[19];
    const float* W_l_mu2 = (const float*)d_in[20];
    const float* b_l_mu2 = (const float*)d_in[21];
    const float* W_r_mu2 = (const float*)d_in[22];
    float* out = (float*)d_out;

    float *mu, *mm;
    __half *x16u, *x16m, *h16u, *h16m;
    cudaGetSymbolAddress((void**)&mu, g_mu);
    cudaGetSymbolAddress((void**)&mm, g_mm);
    cudaGetSymbolAddress((void**)&x16u, g_x16u);
    cudaGetSymbolAddress((void**)&x16m, g_x16m);
    cudaGetSymbolAddress((void**)&h16u, g_h16u);
    cudaGetSymbolAddress((void**)&h16m, g_h16m);

    const int MMA_SMEM = (128 * A_STRIDE + 64 * A_STRIDE) * 2 + 64 * 4;  // 52480B
    const int MI_SMEM = (128 * A_STRIDE + 64 * A_STRIDE) * 2 * 2 + 64 * 4 + 128 * 4;
    cudaFuncSetAttribute(mma_transform_kernel<true>,
                         cudaFuncAttributeMaxDynamicSharedMemorySize, MMA_SMEM);
    cudaFuncSetAttribute(mma_transform_kernel<false>,
                         cudaFuncAttributeMaxDynamicSharedMemorySize, MMA_SMEM);
    cudaFuncSetAttribute(fused_init_kernel,
                         cudaFuncAttributeMaxDynamicSharedMemorySize, MI_SMEM);

    const int NB_M = NB_M_CONST;               // 391
    const int NB_U = (N_USERS + 127) / 128;    // 782

    // launch 0: fused movie_init(MMA) + gather_user + hist; g_deg_* arrive zeroed
    fused_init_kernel<<<NB_M + GU_BLOCKS + HIST_BLOCKS, 256, MI_SMEM>>>(
        movie_x, lin_W, lin_b, movie_emb, movie_nid, x16m,
        user_emb, user_nid, x16u,
        (const int4*)e_src, (const int4*)e_dst);

    // launch 1: scan (writes off+cur, re-zeroes deg)
    scan_kernel<<<2, 1024>>>();

    // launch 2: scatter
    scatter_kernel<<<HIST_BLOCKS, 256>>>((const int4*)e_src, (const int4*)e_dst);

    const int AGG_BLOCKS = ((N_MOVIES + N_USERS) * 16 + 255) / 256;

    // launch 3 (profiled slot): layer-1 aggregate
    aggregate2_kernel<<<AGG_BLOCKS, 256>>>(x16u, x16m, mm, mu);
    mma_transform_kernel<true><<<NB_M + NB_U, 256, MMA_SMEM>>>(
        mm, x16m, W_l_um1, b_l_um1, W_r_um1, h16m, nullptr,
        mu, x16u, W_l_mu1, b_l_mu1, W_r_mu1, h16u, nullptr, NB_M);

    // layer 2 (no activation), fp32 outputs in-place over the mean buffers
    aggregate2_kernel<<<AGG_BLOCKS, 256>>>(h16u, h16m, mm, mu);
    mma_transform_kernel<false><<<NB_M + NB_U, 256, MMA_SMEM>>>(
        mm, h16m, W_l_um2, b_l_um2, W_r_um2, nullptr, mm,
        mu, h16u, W_l_mu2, b_l_mu2, W_r_mu2, nullptr, mu, NB_M);

    // decoder (fp32 finals: users in mu, movies in mm)
    decode_kernel<<<(N_LABEL * 16 + 255) / 256, 256>>>(mu, mm, l_src, l_dst, out, N_LABEL);
}

// round 9
// speedup vs baseline: 1.4822x; 1.0940x over previous
#include <cuda_runtime.h>
#include <cuda_fp16.h>

#define HIDDEN    64
#define N_USERS   100000
#define N_MOVIES  50000
#define MOVIE_FEAT 128
#define N_EDGES   2000000
#define N_LABEL   500000

// padded so the single-block scans can read int4 past n without guards
#define NM_PAD (N_MOVIES + 8192)
#define NU_PAD (N_USERS  + 8192)

// ---------------- device scratch (allocation-free rule: __device__ globals) ----------------
// g_deg_* are zero at module load and re-zeroed by scan_kernel after each consumption,
// so every execution of kernel_launch sees them zeroed.
__device__ __align__(16) int g_deg_m[NM_PAD];
__device__ __align__(16) int g_deg_u[NU_PAD];
__device__ __align__(16) int g_off_m[NM_PAD];
__device__ __align__(16) int g_off_u[NU_PAD];
__device__ __align__(16) int g_cur_m[NM_PAD];
__device__ __align__(16) int g_cur_u[NU_PAD];
__device__ int g_csr_m[N_EDGES];   // neighbors (user idx) of each movie, CSR by movie
__device__ int g_csr_u[N_EDGES];   // neighbors (movie idx) of each user, CSR by user
// fp16 node feature buffers with ONE extra row (index N) that is never written:
// __device__ globals are zero-initialized, every writer guards r < n, so row N is
// permanently zero -> aggregation tails can load it unconditionally.
__device__ __align__(16) __half g_x16u[(N_USERS  + 1) * HIDDEN];
__device__ __align__(16) __half g_x16m[(N_MOVIES + 1) * HIDDEN];
__device__ __align__(16) __half g_h16u[(N_USERS  + 1) * HIDDEN];
__device__ __align__(16) __half g_h16m[(N_MOVIES + 1) * HIDDEN];
__device__ __align__(16) float g_mu[N_USERS  * HIDDEN];
__device__ __align__(16) float g_mm[N_MOVIES * HIDDEN];

// ---------------- packed f32x2 helpers ----------------
__device__ __forceinline__ unsigned long long pack2(float lo, float hi)
{
    unsigned long long r;
    asm("mov.b64 %0, {%1, %2};" : "=l"(r) : "f"(lo), "f"(hi));
    return r;
}
__device__ __forceinline__ void unpack2(unsigned long long v, float& lo, float& hi)
{
    asm("mov.b64 {%0, %1}, %2;" : "=f"(lo), "=f"(hi) : "l"(v));
}
__device__ __forceinline__ unsigned long long fadd2(unsigned long long a,
                                                    unsigned long long b)
{
    unsigned long long d;
    asm("add.rn.f32x2 %0, %1, %2;" : "=l"(d) : "l"(a), "l"(b));
    return d;
}

#define A_STRIDE 136   // halfs per MMA smem row (128 + 8 pad -> conflict-free frag loads)
#define NB_M_CONST ((N_MOVIES + 127) / 128)          // 391 movie-init blocks
#define GU_BLOCKS  ((N_USERS * 16 + 255) / 256)      // 6250 gather blocks
#define HIST_BLOCKS ((N_EDGES / 4 + 255) / 256)      // 1954 hist blocks

// ---------------- fused init: movie_init(MMA) | gather_user | hist ----------------
__global__ __launch_bounds__(256) void fused_init_kernel(
    const float* __restrict__ movie_x, const float* __restrict__ lin_W,
    const float* __restrict__ lin_b,  const float* __restrict__ movie_emb,
    const int* __restrict__ movie_nid, __half* __restrict__ xm16,
    const float* __restrict__ user_emb, const int* __restrict__ user_nid,
    __half* __restrict__ xu16,
    const int4* __restrict__ src4, const int4* __restrict__ dst4)
{
    int tid = threadIdx.x;

    if (blockIdx.x >= NB_M_CONST) {
        int b = blockIdx.x - NB_M_CONST;
        if (b < GU_BLOCKS) {
            // ---- gather_user: x_user = user_emb[user_nid] (fp16) ----
            int i = b * 256 + tid;
            if (i >= N_USERS * 16) return;
            int r = i >> 4, c = i & 15;
            float4 v = __ldg((const float4*)user_emb + __ldg(user_nid + r) * 16 + c);
            __half2 h0 = __floats2half2_rn(v.x, v.y);
            __half2 h1 = __floats2half2_rn(v.z, v.w);
            uint2 o;
            o.x = *(unsigned int*)&h0;
            o.y = *(unsigned int*)&h1;
            ((uint2*)xu16)[i] = o;
        } else {
            // ---- hist: degree histogram of both directions ----
            int i = (b - GU_BLOCKS) * 256 + tid;
            if (i >= N_EDGES / 4) return;
            int4 s = __ldg(src4 + i), d = __ldg(dst4 + i);
            atomicAdd(&g_deg_u[s.x], 1); atomicAdd(&g_deg_u[s.y], 1);
            atomicAdd(&g_deg_u[s.z], 1); atomicAdd(&g_deg_u[s.w], 1);
            atomicAdd(&g_deg_m[d.x], 1); atomicAdd(&g_deg_m[d.y], 1);
            atomicAdd(&g_deg_m[d.z], 1); atomicAdd(&g_deg_m[d.w], 1);
        }
        return;
    }

    // ---- movie_init via tensor cores, hi/lo fp16 split (3 MMAs, fp32-accurate) ----
    extern __shared__ char smem[];
    __half* Ah = (__half*)smem;                    // [128][A_STRIDE]
    __half* Al = Ah + 128 * A_STRIDE;              // [128][A_STRIDE]
    __half* Bh = Al + 128 * A_STRIDE;              // [64][A_STRIDE]
    __half* Bl = Bh + 64 * A_STRIDE;               // [64][A_STRIDE]
    float* bias_s = (float*)(Bl + 64 * A_STRIDE);  // [64]
    int* snid = (int*)(bias_s + 64);               // [128]

    const int n = N_MOVIES;
    int base = blockIdx.x * 128;

    // stage A: 128 rows x 64 float2 = 8192 items
#pragma unroll
    for (int t = 0; t < 32; t++) {
        int idx = t * 256 + tid;
        int r = idx >> 6, p = idx & 63;
        float2 v = make_float2(0.f, 0.f);
        if (base + r < n)
            v = __ldg((const float2*)movie_x + (size_t)(base + r) * 64 + p);
        __half2 hi = __floats2half2_rn(v.x, v.y);
        float2 hf = __half22float2(hi);
        __half2 lo = __floats2half2_rn(v.x - hf.x, v.y - hf.y);
        *(__half2*)(Ah + r * A_STRIDE + 2 * p) = hi;
        *(__half2*)(Al + r * A_STRIDE + 2 * p) = lo;
    }
    // stage B: 64 j-rows x 64 float2 = 4096 items (lin_W is [64][128] row-major)
#pragma unroll
    for (int t = 0; t < 16; t++) {
        int idx = t * 256 + tid;
        int j = idx >> 6, p = idx & 63;
        float2 w = __ldg((const float2*)lin_W + j * 64 + p);
        __half2 hi = __floats2half2_rn(w.x, w.y);
        float2 hf = __half22float2(hi);
        __half2 lo = __floats2half2_rn(w.x - hf.x, w.y - hf.y);
        *(__half2*)(Bh + j * A_STRIDE + 2 * p) = hi;
        *(__half2*)(Bl + j * A_STRIDE + 2 * p) = lo;
    }
    if (tid < 64) bias_s[tid] = __ldg(lin_b + tid);
    if (tid < 128) {
        int r = base + tid;
        snid[tid] = __ldg(movie_nid + (r < n ? r : 0));
    }
    __syncthreads();

    int warp = tid >> 5, lane = tid & 31;
    int grp = lane >> 2, tig = lane & 3;
    int r0 = warp * 16;
    float acc[8][4];
#pragma unroll
    for (int nt = 0; nt < 8; nt++)
#pragma unroll
        for (int c = 0; c < 4; c++) acc[nt][c] = 0.f;

#pragma unroll
    for (int kt = 0; kt < 8; kt++) {
        int ar = r0 + grp, ac = kt * 16 + tig * 2;
        unsigned ah0 = *(const unsigned*)(Ah + ar * A_STRIDE + ac);
        unsigned ah1 = *(const unsigned*)(Ah + (ar + 8) * A_STRIDE + ac);
        unsigned ah2 = *(const unsigned*)(Ah + ar * A_STRIDE + ac + 8);
        unsigned ah3 = *(const unsigned*)(Ah + (ar + 8) * A_STRIDE + ac + 8);
        unsigned al0 = *(const unsigned*)(Al + ar * A_STRIDE + ac);
        unsigned al1 = *(const unsigned*)(Al + (ar + 8) * A_STRIDE + ac);
        unsigned al2 = *(const unsigned*)(Al + ar * A_STRIDE + ac + 8);
        unsigned al3 = *(const unsigned*)(Al + (ar + 8) * A_STRIDE + ac + 8);
#pragma unroll
        for (int nt = 0; nt < 8; nt++) {
            int bn = nt * 8 + grp, bk = kt * 16 + tig * 2;
            unsigned bh0 = *(const unsigned*)(Bh + bn * A_STRIDE + bk);
            unsigned bh1 = *(const unsigned*)(Bh + bn * A_STRIDE + bk + 8);
            unsigned bl0 = *(const unsigned*)(Bl + bn * A_STRIDE + bk);
            unsigned bl1 = *(const unsigned*)(Bl + bn * A_STRIDE + bk + 8);
            asm volatile(
                "mma.sync.aligned.m16n8k16.row.col.f32.f16.f16.f32 "
                "{%0,%1,%2,%3}, {%4,%5,%6,%7}, {%8,%9}, {%0,%1,%2,%3};"
                : "+f"(acc[nt][0]), "+f"(acc[nt][1]), "+f"(acc[nt][2]), "+f"(acc[nt][3])
                : "r"(ah0), "r"(ah1), "r"(ah2), "r"(ah3), "r"(bh0), "r"(bh1));
            asm volatile(
                "mma.sync.aligned.m16n8k16.row.col.f32.f16.f16.f32 "
                "{%0,%1,%2,%3}, {%4,%5,%6,%7}, {%8,%9}, {%0,%1,%2,%3};"
                : "+f"(acc[nt][0]), "+f"(acc[nt][1]), "+f"(acc[nt][2]), "+f"(acc[nt][3])
                : "r"(al0), "r"(al1), "r"(al2), "r"(al3), "r"(bh0), "r"(bh1));
            asm volatile(
                "mma.sync.aligned.m16n8k16.row.col.f32.f16.f16.f32 "
                "{%0,%1,%2,%3}, {%4,%5,%6,%7}, {%8,%9}, {%0,%1,%2,%3};"
                : "+f"(acc[nt][0]), "+f"(acc[nt][1]), "+f"(acc[nt][2]), "+f"(acc[nt][3])
                : "r"(ah0), "r"(ah1), "r"(ah2), "r"(ah3), "r"(bl0), "r"(bl1));
        }
    }

    // epilogue: + bias + movie_emb[nid] gather, fp16 out
#pragma unroll
    for (int nt = 0; nt < 8; nt++) {
        int col = nt * 8 + tig * 2;
        float bj0 = bias_s[col], bj1 = bias_s[col + 1];
        int lr0 = r0 + grp, lr1 = lr0 + 8;
        int gr0 = base + lr0, gr1 = base + lr1;
        if (gr0 < n) {
            float2 e = __ldg((const float2*)movie_emb + (size_t)snid[lr0] * 32 + col / 2);
            *(__half2*)(xm16 + (size_t)gr0 * 64 + col) =
                __floats2half2_rn(acc[nt][0] + bj0 + e.x, acc[nt][1] + bj1 + e.y);
        }
        if (gr1 < n) {
            float2 e = __ldg((const float2*)movie_emb + (size_t)snid[lr1] * 32 + col / 2);
            *(__half2*)(xm16 + (size_t)gr1 * 64 + col) =
                __floats2half2_rn(acc[nt][2] + bj0 + e.x, acc[nt][3] + bj1 + e.y);
        }
    }
}

// block 0 scans movie degrees, block 1 scans user degrees; initializes cursors and
// re-zeroes the degree arrays (each thread zeroes its own chunk after reading it).
__global__ __launch_bounds__(1024) void scan_kernel()
{
    int n; int* deg; int* off; int* cur;
    if (blockIdx.x == 0) { n = N_MOVIES; deg = g_deg_m; off = g_off_m; cur = g_cur_m; }
    else                 { n = N_USERS;  deg = g_deg_u; off = g_off_u; cur = g_cur_u; }
    int chunk = ((((n + 1023) >> 10) + 3) & ~3);   // multiple of 4 for int4
    int t = threadIdx.x;
    int start = t * chunk;

    int s = 0;
    for (int i = 0; i < chunk; i += 4) {
        int4 v = *(const int4*)(deg + start + i);
        s += v.x + v.y + v.z + v.w;
    }
    __shared__ int sh[1024];
    sh[t] = s; __syncthreads();
    for (int d = 1; d < 1024; d <<= 1) {
        int v = (t >= d) ? sh[t - d] : 0;
        __syncthreads();
        sh[t] += v;
        __syncthreads();
    }
    int run = t ? sh[t - 1] : 0;
    int4 z = make_int4(0, 0, 0, 0);
    for (int i = 0; i < chunk; i += 4) {
        int4 v = *(const int4*)(deg + start + i);
        int4 o;
        o.x = run; run += v.x;
        o.y = run; run += v.y;
        o.z = run; run += v.z;
        o.w = run; run += v.w;
        *(int4*)(off + start + i) = o;
        *(int4*)(cur + start + i) = o;
        *(int4*)(deg + start + i) = z;   // ready for the next execution's hist
    }
}

__global__ void scatter_kernel(const int4* __restrict__ src4, const int4* __restrict__ dst4)
{
    int i = blockIdx.x * blockDim.x + threadIdx.x;
    if (i >= N_EDGES / 4) return;
    int4 s = __ldg(src4 + i), d = __ldg(dst4 + i);
    g_csr_m[atomicAdd(&g_cur_m[d.x], 1)] = s.x;
    g_csr_u[atomicAdd(&g_cur_u[s.x], 1)] = d.x;
    g_csr_m[atomicAdd(&g_cur_m[d.y], 1)] = s.y;
    g_csr_u[atomicAdd(&g_cur_u[s.y], 1)] = d.y;
    g_csr_m[atomicAdd(&g_cur_m[d.z], 1)] = s.z;
    g_csr_u[atomicAdd(&g_cur_u[s.z], 1)] = d.z;
    g_csr_m[atomicAdd(&g_cur_m[d.w], 1)] = s.w;
    g_csr_u[atomicAdd(&g_cur_u[s.w], 1)] = d.w;
}

// ---------------- segment mean, quarter-warp per node, fp16 pairwise pre-add --------------
// 8 lanes x uint4 (16B) = one 128B line per row. Tail indices select the permanent zero
// row (index N of the source buffer), so feature loads are unconditional and MLP stays 8
// through the tail. Rows are pre-added in pairs with HADD2 (one extra fp16 rounding per
// pair), then converted and accumulated in packed fp32 -> ~1.5 math inst per edge.
__global__ void aggregate2_kernel(const __half* __restrict__ src_for_m,  // user feats fp16
                                  const __half* __restrict__ src_for_u,  // movie feats fp16
                                  float* __restrict__ out_m, float* __restrict__ out_u)
{
    int q = (blockIdx.x * blockDim.x + threadIdx.x) >> 3;
    int lane = threadIdx.x & 7;
    const uint4* xsrc; const int* csr; const int* off; float4* mean; int node, zrow;
    if (q < N_MOVIES) {
        node = q; xsrc = (const uint4*)src_for_m; csr = g_csr_m; off = g_off_m;
        mean = (float4*)out_m; zrow = N_USERS;
    } else {
        node = q - N_MOVIES;
        if (node >= N_USERS) return;
        xsrc = (const uint4*)src_for_u; csr = g_csr_u; off = g_off_u;
        mean = (float4*)out_u; zrow = N_MOVIES;
    }
    int s0 = __ldg(off + node);
    int deg = __ldg(off + node + 1) - s0;
    const int* nb = csr + s0;

    unsigned long long acc0 = 0, acc1 = 0, acc2 = 0, acc3 = 0;
    int nch = (deg + 7) >> 3;
    int idx[8];
#pragma unroll
    for (int k = 0; k < 8; k++)
        idx[k] = (k < deg) ? __ldg(nb + k) : zrow;
    for (int c = 0; c < nch; c++) {
        uint4 v[8];
#pragma unroll
        for (int k = 0; k < 8; k++)
            v[k] = __ldg(xsrc + (size_t)idx[k] * 8 + lane);
#pragma unroll
        for (int k = 0; k < 8; k++) {
            int i2 = (c + 1) * 8 + k;
            idx[k] = (i2 < deg) ? __ldg(nb + i2) : zrow;
        }
#pragma unroll
        for (int j = 0; j < 4; j++) {
            const uint4& p = v[2 * j];
            const uint4& r = v[2 * j + 1];
            __half2 hx = __hadd2(*(const __half2*)&p.x, *(const __half2*)&r.x);
            __half2 hy = __hadd2(*(const __half2*)&p.y, *(const __half2*)&r.y);
            __half2 hz = __hadd2(*(const __half2*)&p.z, *(const __half2*)&r.z);
            __half2 hw = __hadd2(*(const __half2*)&p.w, *(const __half2*)&r.w);
            float2 fx = __half22float2(hx);
            float2 fy = __half22float2(hy);
            float2 fz = __half22float2(hz);
            float2 fw = __half22float2(hw);
            acc0 = fadd2(acc0, pack2(fx.x, fx.y));
            acc1 = fadd2(acc1, pack2(fy.x, fy.y));
            acc2 = fadd2(acc2, pack2(fz.x, fz.y));
            acc3 = fadd2(acc3, pack2(fw.x, fw.y));
        }
    }
    float f0, f1, f2, f3, f4, f5, f6, f7;
    unpack2(acc0, f0, f1); unpack2(acc1, f2, f3);
    unpack2(acc2, f4, f5); unpack2(acc3, f6, f7);
    float inv = deg > 0 ? 1.0f / (float)deg : 0.0f;   // deg==0 -> mean 0, matches reference
    float4 o0, o1;
    o0.x = f0 * inv; o0.y = f1 * inv; o0.z = f2 * inv; o0.w = f3 * inv;
    o1.x = f4 * inv; o1.y = f5 * inv; o1.z = f6 * inv; o1.w = f7 * inv;
    mean[(size_t)node * 16 + lane * 2] = o0;
    mean[(size_t)node * 16 + lane * 2 + 1] = o1;
}

// ---------------- SAGE transform via mma.sync m16n8k16 (fp16 in, fp32 accum) --------------
template<bool L1>
__global__ __launch_bounds__(256) void mma_transform_kernel(
    const float* __restrict__ mean_m, const __half* __restrict__ xd_m,
    const float* __restrict__ Wl_m, const float* __restrict__ bl_m,
    const float* __restrict__ Wr_m, __half* __restrict__ o16_m, float* __restrict__ o32_m,
    const float* __restrict__ mean_u, const __half* __restrict__ xd_u,
    const float* __restrict__ Wl_u, const float* __restrict__ bl_u,
    const float* __restrict__ Wr_u, __half* __restrict__ o16_u, float* __restrict__ o32_u,
    int nb_m)
{
    extern __shared__ char smem[];
    __half* As = (__half*)smem;                       // [128][A_STRIDE]
    __half* Bs = As + 128 * A_STRIDE;                 // [64][A_STRIDE]
    float* bias_s = (float*)(Bs + 64 * A_STRIDE);     // [64]

    const float *mean, *Wl, *bl, *Wr; const __half* xd; __half* o16; float* o32;
    int n, base;
    if ((int)blockIdx.x < nb_m) {
        mean = mean_m; xd = xd_m; Wl = Wl_m; bl = bl_m; Wr = Wr_m;
        o16 = o16_m; o32 = o32_m; n = N_MOVIES; base = blockIdx.x * 128;
    } else {
        mean = mean_u; xd = xd_u; Wl = Wl_u; bl = bl_u; Wr = Wr_u;
        o16 = o16_u; o32 = o32_u; n = N_USERS; base = (blockIdx.x - nb_m) * 128;
    }
    int tid = threadIdx.x;

    // stage B: 64 j-rows x 64 half2 pairs
#pragma unroll
    for (int t = 0; t < 16; t++) {
        int idx = t * 256 + tid;
        int j = idx >> 6, p = idx & 63;
        int k = 2 * p;
        float2 w;
        if (k < 64) w = __ldg((const float2*)(Wl + j * 64 + k));
        else        w = __ldg((const float2*)(Wr + j * 64 + (k - 64)));
        *(__half2*)(Bs + j * A_STRIDE + k) = __floats2half2_rn(w.x, w.y);
    }
    if (tid < 64) bias_s[tid] = __ldg(bl + tid);

    // stage A mean part: 128 rows x 32 half2 pairs (cols 0..63)
#pragma unroll
    for (int t = 0; t < 16; t++) {
        int idx = t * 256 + tid;
        int r = idx >> 5, p = idx & 31;
        __half2 h = __floats2half2_rn(0.f, 0.f);
        if (base + r < n) {
            float2 v = __ldg((const float2*)(mean + (size_t)(base + r) * 64 + 2 * p));
            h = __floats2half2_rn(v.x, v.y);
        }
        *(__half2*)(As + r * A_STRIDE + 2 * p) = h;
    }
    // stage A x part: 128 rows x 8 uint4 (cols 64..127, fp16 direct)
#pragma unroll
    for (int t = 0; t < 4; t++) {
        int idx = t * 256 + tid;
        int r = idx >> 3, q = idx & 7;
        uint4 u = make_uint4(0, 0, 0, 0);
        if (base + r < n)
            u = __ldg((const uint4*)(xd + (size_t)(base + r) * 64) + q);
        *(uint4*)(As + r * A_STRIDE + 64 + q * 8) = u;
    }
    __syncthreads();

    int warp = tid >> 5, lane = tid & 31;
    int grp = lane >> 2, tig = lane & 3;
    int r0 = warp * 16;
    float acc[8][4];
#pragma unroll
    for (int nt = 0; nt < 8; nt++)
#pragma unroll
        for (int c = 0; c < 4; c++) acc[nt][c] = 0.f;

#pragma unroll
    for (int kt = 0; kt < 8; kt++) {
        int ar = r0 + grp, ac = kt * 16 + tig * 2;
        unsigned a0 = *(const unsigned*)(As + ar * A_STRIDE + ac);
        unsigned a1 = *(const unsigned*)(As + (ar + 8) * A_STRIDE + ac);
        unsigned a2 = *(const unsigned*)(As + ar * A_STRIDE + ac + 8);
        unsigned a3 = *(const unsigned*)(As + (ar + 8) * A_STRIDE + ac + 8);
#pragma unroll
        for (int nt = 0; nt < 8; nt++) {
            int bn = nt * 8 + grp, bk = kt * 16 + tig * 2;
            unsigned b0 = *(const unsigned*)(Bs + bn * A_STRIDE + bk);
            unsigned b1 = *(const unsigned*)(Bs + bn * A_STRIDE + bk + 8);
            asm volatile(
                "mma.sync.aligned.m16n8k16.row.col.f32.f16.f16.f32 "
                "{%0,%1,%2,%3}, {%4,%5,%6,%7}, {%8,%9}, {%0,%1,%2,%3};"
                : "+f"(acc[nt][0]), "+f"(acc[nt][1]), "+f"(acc[nt][2]), "+f"(acc[nt][3])
                : "r"(a0), "r"(a1), "r"(a2), "r"(a3), "r"(b0), "r"(b1));
        }
    }

    // epilogue
#pragma unroll
    for (int nt = 0; nt < 8; nt++) {
        int col = nt * 8 + tig * 2;
        float bj0 = bias_s[col], bj1 = bias_s[col + 1];
        int gr0 = base + r0 + grp;
        int gr1 = gr0 + 8;
        float v00 = acc[nt][0] + bj0, v01 = acc[nt][1] + bj1;
        float v10 = acc[nt][2] + bj0, v11 = acc[nt][3] + bj1;
        if (L1) {
            v00 = fmaxf(v00, 0.f); v01 = fmaxf(v01, 0.f);
            v10 = fmaxf(v10, 0.f); v11 = fmaxf(v11, 0.f);
            if (gr0 < n) *(__half2*)(o16 + (size_t)gr0 * 64 + col) = __floats2half2_rn(v00, v01);
            if (gr1 < n) *(__half2*)(o16 + (size_t)gr1 * 64 + col) = __floats2half2_rn(v10, v11);
        } else {
            if (gr0 < n) *(float2*)(o32 + (size_t)gr0 * 64 + col) = make_float2(v00, v01);
            if (gr1 < n) *(float2*)(o32 + (size_t)gr1 * 64 + col) = make_float2(v10, v11);
        }
    }
}

// ---------------- dot-product decoder (half-warp per edge, fp32 inputs) ----------------
__global__ void decode_kernel(const float* __restrict__ ou, const float* __restrict__ om,
                              const int* __restrict__ ls, const int* __restrict__ ld,
                              float* __restrict__ out, int n)
{
    int e = (blockIdx.x * blockDim.x + threadIdx.x) >> 4;
    int lane = threadIdx.x & 15;
    if (e >= n) return;
    int u = __ldg(ls + e), m = __ldg(ld + e);
    float4 a = __ldg((const float4*)ou + (size_t)u * 16 + lane);
    float4 b = __ldg((const float4*)om + (size_t)m * 16 + lane);
    float p = a.x * b.x + a.y * b.y + a.z * b.z + a.w * b.w;
    p += __shfl_xor_sync(0xffffffffu, p, 1);
    p += __shfl_xor_sync(0xffffffffu, p, 2);
    p += __shfl_xor_sync(0xffffffffu, p, 4);
    p += __shfl_xor_sync(0xffffffffu, p, 8);
    if (lane == 0) out[e] = p;
}

// ---------------- launch ----------------
extern "C" void kernel_launch(void* const* d_in, const int* in_sizes, int n_in,
                              void* d_out, int out_size)
{
    const float* movie_x   = (const float*)d_in[0];
    const int*   user_nid  = (const int*)d_in[1];
    const int*   movie_nid = (const int*)d_in[2];
    const int*   e_src     = (const int*)d_in[3];
    const int*   e_dst     = (const int*)d_in[4];
    const int*   l_src     = (const int*)d_in[5];
    const int*   l_dst     = (const int*)d_in[6];
    const float* user_emb  = (const float*)d_in[7];
    const float* movie_emb = (const float*)d_in[8];
    const float* lin_W     = (const float*)d_in[9];
    const float* lin_b     = (const float*)d_in[10];
    const float* W_l_um1 = (const float*)d_in[11];
    const float* b_l_um1 = (const float*)d_in[12];
    const float* W_r_um1 = (const float*)d_in[13];
    const float* W_l_mu1 = (const float*)d_in[14];
    const float* b_l_mu1 = (const float*)d_in[15];
    const float* W_r_mu1 = (const float*)d_in[16];
    const float* W_l_um2 = (const float*)d_in[17];
    const float* b_l_um2 = (const float*)d_in[18];
    const float* W_r_um2 = (const float*)d_in[19];
    const float* W_l_mu2 = (const float*)d_in[20];
    const float* b_l_mu2 = (const float*)d_in[21];
    const float* W_r_mu2 = (const float*)d_in[22];
    float* out = (float*)d_out;

    float *mu, *mm;
    __half *x16u, *x16m, *h16u, *h16m;
    cudaGetSymbolAddress((void**)&mu, g_mu);
    cudaGetSymbolAddress((void**)&mm, g_mm);
    cudaGetSymbolAddress((void**)&x16u, g_x16u);
    cudaGetSymbolAddress((void**)&x16m, g_x16m);
    cudaGetSymbolAddress((void**)&h16u, g_h16u);
    cudaGetSymbolAddress((void**)&h16m, g_h16m);

    const int MMA_SMEM = (128 * A_STRIDE + 64 * A_STRIDE) * 2 + 64 * 4;  // 52480B
    const int MI_SMEM = (128 * A_STRIDE + 64 * A_STRIDE) * 2 * 2 + 64 * 4 + 128 * 4;
    cudaFuncSetAttribute(mma_transform_kernel<true>,
                         cudaFuncAttributeMaxDynamicSharedMemorySize, MMA_SMEM);
    cudaFuncSetAttribute(mma_transform_kernel<false>,
                         cudaFuncAttributeMaxDynamicSharedMemorySize, MMA_SMEM);
    cudaFuncSetAttribute(fused_init_kernel,
                         cudaFuncAttributeMaxDynamicSharedMemorySize, MI_SMEM);

    const int NB_M = NB_M_CONST;               // 391
    const int NB_U = (N_USERS + 127) / 128;    // 782

    // launch 0: fused movie_init(MMA) + gather_user + hist; g_deg_* arrive zeroed
    fused_init_kernel<<<NB_M + GU_BLOCKS + HIST_BLOCKS, 256, MI_SMEM>>>(
        movie_x, lin_W, lin_b, movie_emb, movie_nid, x16m,
        user_emb, user_nid, x16u,
        (const int4*)e_src, (const int4*)e_dst);

    // launch 1: scan (writes off+cur, re-zeroes deg)
    scan_kernel<<<2, 1024>>>();

    // launch 2: scatter
    scatter_kernel<<<HIST_BLOCKS, 256>>>((const int4*)e_src, (const int4*)e_dst);

    const int AGG_BLOCKS = ((N_MOVIES + N_USERS) * 8 + 255) / 256;

    // launch 3 (profiled slot): layer-1 aggregate
    aggregate2_kernel<<<AGG_BLOCKS, 256>>>(x16u, x16m, mm, mu);
    mma_transform_kernel<true><<<NB_M + NB_U, 256, MMA_SMEM>>>(
        mm, x16m, W_l_um1, b_l_um1, W_r_um1, h16m, nullptr,
        mu, x16u, W_l_mu1, b_l_mu1, W_r_mu1, h16u, nullptr, NB_M);

    // layer 2 (no activation), fp32 outputs in-place over the mean buffers
    aggregate2_kernel<<<AGG_BLOCKS, 256>>>(h16u, h16m, mm, mu);
    mma_transform_kernel<false><<<NB_M + NB_U, 256, MMA_SMEM>>>(
        mm, h16m, W_l_um2, b_l_um2, W_r_um2, nullptr, mm,
        mu, h16u, W_l_mu2, b_l_mu2, W_r_mu2, nullptr, mu, NB_M);

    // decoder (fp32 finals: users in mu, movies in mm)
    decode_kernel<<<(N_LABEL * 16 + 255) / 256, 256>>>(mu, mm, l_src, l_dst, out, N_LABEL);
}